// round 4
// baseline (speedup 1.0000x reference)
#include <cuda_runtime.h>
#include <cuda_bf16.h>

// Problem constants
#define BQ   4096
#define NQ   32
#define HQ   256
#define DINQ 256
#define RQ   3
#define KQ   (DINQ + HQ)   // 512
#define VIRTUAL_DECAY 0.7f
#define MB   16            // batches per CTA in gate kernel
#define CTS  18            // combT row stride (floats)
#define ROWS_TOT (BQ * NQ) // 131072

// GEMM tiling
#define GM 128
#define GN 128
#define GK 32
#define NKS (HQ / GK)      // 8 k-steps
#define ASTR (GK + 4)      // 36
#define BSTR (GN + 4)      // 132
#define AS_FLOATS (2 * GM * ASTR)   // 9216
#define BS_FLOATS (2 * GK * BSTR)   // 8448
#define FGEMM_SMEM ((AS_FLOATS + BS_FLOATS + 128 + 128) * 4)   // ~71.7 KB

// -------- packed dual-fp32 helpers (sm_103a FFMA2) --------
__device__ __forceinline__ unsigned long long pack2(float x, float y) {
    unsigned long long r;
    asm("mov.b64 %0, {%1, %2};" : "=l"(r) : "f"(x), "f"(y));
    return r;
}
__device__ __forceinline__ void fma2(unsigned long long& d,
                                     unsigned long long a, unsigned long long b) {
    asm("fma.rn.f32x2 %0, %1, %2, %3;" : "=l"(d) : "l"(a), "l"(b), "l"(d));
}
__device__ __forceinline__ float2 unpack2(unsigned long long v) {
    float2 r;
    asm("mov.b64 {%0, %1}, %2;" : "=f"(r.x), "=f"(r.y) : "l"(v));
    return r;
}

// -------- device scratch (no dynamic allocation allowed) --------
__device__ float g_WfT[RQ * HQ * HQ];   // [r][h][g]
__device__ float g_WiT[KQ * HQ];        // [k][g]
__device__ float g_WoT[KQ * HQ];
__device__ float g_WuT[KQ * HQ];
__device__ float g_hs[BQ * HQ];         // child_h_sum
__device__ float g_cs[BQ * HQ];         // child_c_sum
__device__ float g_f[(size_t)ROWS_TOT * HQ];   // f gate results, [b][n][g]
__device__ float g_dec[ROWS_TOT];       // decay per row
__device__ int   g_idxr[RQ][ROWS_TOT];  // row indices grouped by relation
__device__ int   g_cnt[RQ];
__device__ int   g_mmode;               // virtual_mask storage dtype

__device__ __forceinline__ float load_dec(const void* vmask, int i, int mmode) {
    bool mv;
    if (mmode == 0)      mv = ((const int*)vmask)[i] != 0;
    else if (mmode == 1) mv = ((const unsigned char*)vmask)[i] != 0;
    else                 mv = ((const float*)vmask)[i] != 0.0f;
    return mv ? VIRTUAL_DECAY : 1.0f;
}

// -------- prep1: transposes + mask dtype detection + zero counters --------
__global__ __launch_bounds__(256) void prep1_kernel(
    const float* __restrict__ Wf, const float* __restrict__ Wi,
    const float* __restrict__ Wo, const float* __restrict__ Wu,
    const void* __restrict__ vmask)
{
    int idx = blockIdx.x * 256 + threadIdx.x;
    if (idx < RQ * HQ * HQ) {
        int h = idx & (HQ - 1);
        int g = (idx >> 8) & (HQ - 1);
        int r = idx >> 16;
        g_WfT[(r * HQ + h) * HQ + g] = Wf[idx];        // Wf[r][g][h]
    }
    if (idx < KQ * HQ) {
        int g = idx & (HQ - 1);
        int k = idx >> 8;
        g_WiT[idx] = Wi[g * KQ + k];
        g_WoT[idx] = Wo[g * KQ + k];
        g_WuT[idx] = Wu[g * KQ + k];
    }
    if (blockIdx.x == 0) {
        __shared__ int fl[2];
        int tid = threadIdx.x;
        if (tid < 2) fl[tid] = 0;
        if (tid < RQ) g_cnt[tid] = 0;
        __syncthreads();
        const unsigned char* mb = (const unsigned char*)vmask;
        for (int off = tid; off < 8192; off += 256) {
            int m = off & 3;
            unsigned char v = mb[off];
            if (m && v) {
                fl[0] = 1;                                     // non-aligned nonzero -> not i32
                if ((m == 2 && v == 0x80u) || (m == 3 && v == 0x3Fu))
                    fl[1] = 1;                                 // 1.0f byte pattern -> f32
            }
        }
        __syncthreads();
        if (tid == 0) g_mmode = fl[1] ? 2 : (fl[0] ? 1 : 0);   // 0=i32, 1=u8, 2=f32
    }
}

// -------- prep2: decay + counting-sort rows by relation --------
__global__ __launch_bounds__(256) void prep2_kernel(
    const int* __restrict__ rel_ids, const void* __restrict__ vmask)
{
    int i = blockIdx.x * 256 + threadIdx.x;
    if (i >= ROWS_TOT) return;
    int mmode = g_mmode;
    g_dec[i] = load_dec(vmask, i, mmode);
    int r = rel_ids[i];
    int pos = atomicAdd(&g_cnt[r], 1);
    g_idxr[r][pos] = i;
}

// -------- fgemm: F_r = gather(CH)_r x W_r^T, decay applied in epilogue --------
// grid: (g-tiles, row-tiles, relations) so both g-tiles of a row tile are adjacent
extern __shared__ float smG[];

__global__ __launch_bounds__(256, 2) void fgemm_kernel(
    const float* __restrict__ child_h)
{
    const int by = blockIdx.x;           // g tile (0..1)
    const int bx = blockIdx.y;           // row tile
    const int bz = blockIdx.z;           // relation
    const int cnt = g_cnt[bz];
    const int row0 = bx * GM;
    if (row0 >= cnt) return;

    float* As    = smG;                              // [2][GM][ASTR]
    float* Bs    = smG + AS_FLOATS;                  // [2][GK][BSTR]
    int*   s_idx = (int*)(smG + AS_FLOATS + BS_FLOATS);
    float* s_dec = (float*)(s_idx + 128);

    const int tid = threadIdx.x;
    const int tx  = tid & 15;
    const int ty  = tid >> 4;

    if (tid < 128) {
        int rr = row0 + tid;
        if (rr >= cnt) rr = cnt - 1;
        int gi = g_idxr[bz][rr];
        s_idx[tid] = gi;
        s_dec[tid] = g_dec[gi];
    }
    __syncthreads();

    auto stage = [&](int ks, int buf) {
        #pragma unroll
        for (int i = 0; i < 4; i++) {
            int v = tid + i * 256;           // 0..1023
            int m = v >> 3;                  // row in tile
            int c = v & 7;                   // float4 within 32-k chunk
            const float* src = child_h + (size_t)s_idx[m] * HQ + ks * GK + c * 4;
            unsigned dst = (unsigned)__cvta_generic_to_shared(
                As + (buf * GM + m) * ASTR + c * 4);
            asm volatile("cp.async.cg.shared.global [%0], [%1], 16;\n"
                         :: "r"(dst), "l"(src));
        }
        #pragma unroll
        for (int i = 0; i < 4; i++) {
            int v = tid + i * 256;
            int k = v >> 5;
            int c = v & 31;
            const float* src = g_WfT + ((size_t)(bz * HQ + ks * GK + k)) * HQ + by * GN + c * 4;
            unsigned dst = (unsigned)__cvta_generic_to_shared(
                Bs + (buf * GK + k) * BSTR + c * 4);
            asm volatile("cp.async.cg.shared.global [%0], [%1], 16;\n"
                         :: "r"(dst), "l"(src));
        }
        asm volatile("cp.async.commit_group;\n");
    };

    unsigned long long acc2[32];         // [8 rows][4 g-pairs]
    #pragma unroll
    for (int i = 0; i < 32; i++) acc2[i] = 0ull;

    stage(0, 0);

    for (int ks = 0; ks < NKS; ks++) {
        if (ks + 1 < NKS) {
            stage(ks + 1, (ks + 1) & 1);
            asm volatile("cp.async.wait_group 1;\n");
        } else {
            asm volatile("cp.async.wait_group 0;\n");
        }
        __syncthreads();

        const float* Ab = As + (ks & 1) * GM * ASTR;
        const float* Bb = Bs + (ks & 1) * GK * BSTR;

        #pragma unroll 8
        for (int kk = 0; kk < GK; kk++) {
            // 8 b-values = 4 packed pairs (adjacent g pairs, 8B-aligned in smem)
            double2 b0 = *(const double2*)(Bb + kk * BSTR + tx * 4);
            double2 b1 = *(const double2*)(Bb + kk * BSTR + 64 + tx * 4);
            unsigned long long bp0 = __double_as_longlong(b0.x);
            unsigned long long bp1 = __double_as_longlong(b0.y);
            unsigned long long bp2 = __double_as_longlong(b1.x);
            unsigned long long bp3 = __double_as_longlong(b1.y);
            #pragma unroll
            for (int i = 0; i < 8; i++) {
                float av = (i < 4) ? Ab[(ty * 4 + i) * ASTR + kk]
                                   : Ab[(64 + ty * 4 + (i - 4)) * ASTR + kk];
                unsigned long long a2 = pack2(av, av);
                fma2(acc2[i * 4 + 0], a2, bp0);
                fma2(acc2[i * 4 + 1], a2, bp1);
                fma2(acc2[i * 4 + 2], a2, bp2);
                fma2(acc2[i * 4 + 3], a2, bp3);
            }
        }
        __syncthreads();
    }

    // epilogue: scale by decay, scatter to g_f[row][g]
    #pragma unroll
    for (int i = 0; i < 8; i++) {
        int m = (i < 4) ? (ty * 4 + i) : (64 + ty * 4 + (i - 4));
        if (row0 + m < cnt) {
            int   row = s_idx[m];
            float d   = s_dec[m];
            float* dst = g_f + (size_t)row * HQ + by * GN;
            float2 p0 = unpack2(acc2[i * 4 + 0]);
            float2 p1 = unpack2(acc2[i * 4 + 1]);
            float2 p2 = unpack2(acc2[i * 4 + 2]);
            float2 p3 = unpack2(acc2[i * 4 + 3]);
            *(float4*)(dst + tx * 4)      = make_float4(p0.x * d, p0.y * d, p1.x * d, p1.y * d);
            *(float4*)(dst + 64 + tx * 4) = make_float4(p2.x * d, p2.y * d, p3.x * d, p3.y * d);
        }
    }
}

// -------- combine: attention + child_h_sum + child_c_sum --------
__global__ __launch_bounds__(256) void combine_kernel(
    const float* __restrict__ child_h, const float* __restrict__ child_c,
    const int*   __restrict__ rel_ids, const float* __restrict__ rel_emb,
    const float* __restrict__ w_att,   const float* __restrict__ b_att,
    const float* __restrict__ b_f)
{
    __shared__ float sch[NQ][264];        // decayed child_h
    __shared__ float s_sc[32], s_dec[32];
    __shared__ int   s_rel[32];

    const int b = blockIdx.x, tid = threadIdx.x;
    const int warp = tid >> 5, lane = tid & 31;

    if (tid < NQ) {
        int i = b * NQ + tid;
        s_rel[tid] = rel_ids[i];
        s_dec[tid] = g_dec[i];
    }
    __syncthreads();

    {
        const float4* gh = (const float4*)(child_h + (size_t)b * NQ * HQ);
        #pragma unroll
        for (int k = 0; k < 8; k++) {
            int v  = tid + k * 256;
            int n  = v >> 6;
            int h4 = v & 63;
            float d = s_dec[n];
            float4 a = gh[v];
            a.x *= d; a.y *= d; a.z *= d; a.w *= d;
            *((float4*)&sch[n][h4 * 4]) = a;
        }
    }
    __syncthreads();

    {
        float batt = b_att[0];
        for (int nn = warp * 4; nn < warp * 4 + 4; nn++) {
            const float* rrow = rel_emb + s_rel[nn] * HQ;
            float p = 0.0f;
            #pragma unroll
            for (int h = lane; h < HQ; h += 32)
                p += (rrow[h] + sch[nn][h]) * w_att[h];
            #pragma unroll
            for (int o = 16; o; o >>= 1) p += __shfl_xor_sync(0xffffffffu, p, o);
            if (lane == 0) s_sc[nn] = p + batt;
        }
    }
    __syncthreads();

    if (warp == 0) {
        float s = s_sc[lane], m = s;
        #pragma unroll
        for (int o = 16; o; o >>= 1) m = fmaxf(m, __shfl_xor_sync(0xffffffffu, m, o));
        float e = __expf(s - m), su = e;
        #pragma unroll
        for (int o = 16; o; o >>= 1) su += __shfl_xor_sync(0xffffffffu, su, o);
        s_sc[lane] = e / su;
    }
    __syncthreads();

    {
        int g = tid;
        float bf0 = b_f[g], bf1 = b_f[HQ + g], bf2 = b_f[2 * HQ + g];
        const float* cc = child_c + (size_t)b * NQ * HQ + g;
        const float* ff = g_f + (size_t)b * NQ * HQ + g;
        float hacc0 = 0.0f, hacc1 = 0.0f, cacc0 = 0.0f, cacc1 = 0.0f;
        #pragma unroll
        for (int n = 0; n < NQ; n += 2) {
            float f0 = ff[n * HQ],       c0 = cc[n * HQ];
            float f1 = ff[(n + 1) * HQ], c1 = cc[(n + 1) * HQ];
            hacc0 += s_sc[n]     * sch[n][g];
            hacc1 += s_sc[n + 1] * sch[n + 1][g];
            int r0 = s_rel[n], r1 = s_rel[n + 1];
            float bfa = (r0 == 0) ? bf0 : ((r0 == 1) ? bf1 : bf2);
            float bfb = (r1 == 0) ? bf0 : ((r1 == 1) ? bf1 : bf2);
            cacc0 += (f0 + bfa) * (c0 * s_dec[n]);
            cacc1 += (f1 + bfb) * (c1 * s_dec[n + 1]);
        }
        g_hs[(size_t)b * HQ + g] = hacc0 + hacc1;
        g_cs[(size_t)b * HQ + g] = cacc0 + cacc1;
    }
}

// -------- gates GEMVs (packed f32x2) + pointwise epilogue --------
__global__ __launch_bounds__(256) void gates_kernel(
    const float* __restrict__ input_vec,
    const float* __restrict__ b_i, const float* __restrict__ b_o,
    const float* __restrict__ b_u, float* __restrict__ out)
{
    __shared__ float combT[KQ * CTS];    // [k][m], stride 18
    const int tid = threadIdx.x;
    const int b0  = blockIdx.x * MB;

    #pragma unroll
    for (int it = 0; it < MB * KQ / 4 / 256; it++) {
        int v  = tid + it * 256;
        int m  = v >> 7;
        int k4 = v & 127;
        int bb = b0 + m;
        float4 val;
        if (k4 < 64) val = ((const float4*)(input_vec + (size_t)bb * DINQ))[k4];
        else         val = ((const float4*)(g_hs      + (size_t)bb * HQ))[k4 - 64];
        combT[(k4 * 4 + 0) * CTS + m] = val.x;
        combT[(k4 * 4 + 1) * CTS + m] = val.y;
        combT[(k4 * 4 + 2) * CTS + m] = val.z;
        combT[(k4 * 4 + 3) * CTS + m] = val.w;
    }
    __syncthreads();

    const int g = tid;
    unsigned long long ai2[MB / 2], ao2[MB / 2], au2[MB / 2];
    #pragma unroll
    for (int m = 0; m < MB / 2; m++) { ai2[m] = 0ull; ao2[m] = 0ull; au2[m] = 0ull; }

    const float* wi = g_WiT + g;
    const float* wo = g_WoT + g;
    const float* wu = g_WuT + g;

    #pragma unroll 4
    for (int k = 0; k < KQ; k++) {
        unsigned long long vi2 = pack2(wi[(size_t)k * HQ], wi[(size_t)k * HQ]);
        unsigned long long vo2 = pack2(wo[(size_t)k * HQ], wo[(size_t)k * HQ]);
        unsigned long long vu2 = pack2(wu[(size_t)k * HQ], wu[(size_t)k * HQ]);
        const double* crow = (const double*)(combT + k * CTS);
        #pragma unroll
        for (int m = 0; m < MB / 2; m++) {
            unsigned long long cm2 = __double_as_longlong(crow[m]);
            fma2(ai2[m], vi2, cm2);
            fma2(ao2[m], vo2, cm2);
            fma2(au2[m], vu2, cm2);
        }
    }

    float bi = b_i[g], bo = b_o[g], bu = b_u[g];
    #pragma unroll
    for (int mp = 0; mp < MB / 2; mp++) {
        float2 pi = unpack2(ai2[mp]);
        float2 po = unpack2(ao2[mp]);
        float2 pu = unpack2(au2[mp]);
        #pragma unroll
        for (int s = 0; s < 2; s++) {
            int m  = mp * 2 + s;
            int bb = b0 + m;
            float av = s ? pi.y : pi.x;
            float ov = s ? po.y : po.x;
            float uv = s ? pu.y : pu.x;
            float iv = 1.0f / (1.0f + __expf(-(av + bi)));
            float og = 1.0f / (1.0f + __expf(-(ov + bo)));
            float ug = tanhf(uv + bu);
            float c  = iv * ug + g_cs[(size_t)bb * HQ + g];
            float h  = og * tanhf(c);
            out[(size_t)bb * HQ + g]                   = h;
            out[(size_t)BQ * HQ + (size_t)bb * HQ + g] = c;
        }
    }
}

// -------- launch --------
extern "C" void kernel_launch(void* const* d_in, const int* in_sizes, int n_in,
                              void* d_out, int out_size) {
    const float* input_vec = (const float*)d_in[0];
    const float* child_h   = (const float*)d_in[1];
    const float* child_c   = (const float*)d_in[2];
    const int*   rel_ids   = (const int*)  d_in[3];
    const void*  vmask     =               d_in[4];
    const float* rel_emb   = (const float*)d_in[5];
    const float* W_i       = (const float*)d_in[6];
    const float* b_i       = (const float*)d_in[7];
    const float* W_f       = (const float*)d_in[8];
    const float* b_f       = (const float*)d_in[9];
    const float* W_o       = (const float*)d_in[10];
    const float* b_o       = (const float*)d_in[11];
    const float* W_u       = (const float*)d_in[12];
    const float* b_u       = (const float*)d_in[13];
    const float* w_att     = (const float*)d_in[14];
    const float* b_att     = (const float*)d_in[15];
    float* out = (float*)d_out;

    prep1_kernel<<<(RQ * HQ * HQ + 255) / 256, 256>>>(W_f, W_i, W_o, W_u, vmask);
    prep2_kernel<<<ROWS_TOT / 256, 256>>>(rel_ids, vmask);

    cudaFuncSetAttribute(fgemm_kernel,
                         cudaFuncAttributeMaxDynamicSharedMemorySize, FGEMM_SMEM);
    dim3 ggrid(HQ / GN, (ROWS_TOT + GM - 1) / GM, RQ);
    fgemm_kernel<<<ggrid, 256, FGEMM_SMEM>>>(child_h);

    combine_kernel<<<BQ, 256>>>(child_h, child_c, rel_ids, rel_emb,
                                w_att, b_att, b_f);

    gates_kernel<<<BQ / MB, 256>>>(input_vec, b_i, b_o, b_u, out);
}

// round 7
// speedup vs baseline: 1.3207x; 1.3207x over previous
#include <cuda_runtime.h>
#include <cuda_bf16.h>
#include <cstdint>

// Problem constants
#define BQ   4096
#define NQ   32
#define HQ   256
#define DINQ 256
#define RQ   3
#define KQ   (DINQ + HQ)   // 512
#define VIRTUAL_DECAY 0.7f
#define MB   16            // batches per CTA in gate kernel
#define ROWS_TOT (BQ * NQ) // 131072

// mma fgemm tiling
#define TM 128             // rows per CTA tile
#define TN 128             // g per CTA tile
#define KCH 64             // k per staged chunk
#define NCH (HQ / KCH)     // 4 chunks

// smem frag layout (uint32 offsets from frag base)
#define F_AH 0
#define F_AL 4096          // 16KB / 4
#define F_BH 8192
#define F_BL 12288
#define FG_SMEM (1024 + 65536)   // idx/dec + 4x16KB frags

// -------- device scratch (no dynamic allocation allowed) --------
__device__ __nv_bfloat16 g_Wfh[RQ * HQ * HQ];  // W_f split, [r][g][h] (natural layout)
__device__ __nv_bfloat16 g_Wfl[RQ * HQ * HQ];
__device__ float g_WiT[KQ * HQ];        // [k][g]
__device__ float g_WoT[KQ * HQ];
__device__ float g_WuT[KQ * HQ];
__device__ float g_hs[BQ * HQ];         // child_h_sum
__device__ float g_cs[BQ * HQ];         // child_c_sum
__device__ float g_f[(size_t)ROWS_TOT * HQ];   // f gate results, [b][n][g]
__device__ float g_dec[ROWS_TOT];       // decay per row
__device__ int   g_idxr[RQ][ROWS_TOT];  // row indices grouped by relation
__device__ int   g_cnt[RQ];
__device__ int   g_mmode;               // virtual_mask storage dtype

__device__ __forceinline__ uint32_t pack_bf16x2(float x, float y) {
    __nv_bfloat16 a = __float2bfloat16_rn(x);
    __nv_bfloat16 b = __float2bfloat16_rn(y);
    return (uint32_t)__bfloat16_as_ushort(a) | ((uint32_t)__bfloat16_as_ushort(b) << 16);
}
__device__ __forceinline__ void mma_bf16(float* c, const uint32_t* a, const uint32_t* b) {
    asm volatile(
        "mma.sync.aligned.m16n8k16.row.col.f32.bf16.bf16.f32 "
        "{%0,%1,%2,%3}, {%4,%5,%6,%7}, {%8,%9}, {%0,%1,%2,%3};"
        : "+f"(c[0]), "+f"(c[1]), "+f"(c[2]), "+f"(c[3])
        : "r"(a[0]), "r"(a[1]), "r"(a[2]), "r"(a[3]), "r"(b[0]), "r"(b[1]));
}

__device__ __forceinline__ float load_dec(const void* vmask, int i, int mmode) {
    bool mv;
    if (mmode == 0)      mv = ((const int*)vmask)[i] != 0;
    else if (mmode == 1) mv = ((const unsigned char*)vmask)[i] != 0;
    else                 mv = ((const float*)vmask)[i] != 0.0f;
    return mv ? VIRTUAL_DECAY : 1.0f;
}

// -------- prep1: weight split + gate transposes + mask dtype + zero counters --------
__global__ __launch_bounds__(256) void prep1_kernel(
    const float* __restrict__ Wf, const float* __restrict__ Wi,
    const float* __restrict__ Wo, const float* __restrict__ Wu,
    const void* __restrict__ vmask)
{
    int idx = blockIdx.x * 256 + threadIdx.x;
    if (idx < RQ * HQ * HQ) {
        float x = Wf[idx];
        __nv_bfloat16 h = __float2bfloat16_rn(x);
        float r = x - __bfloat162float(h);
        g_Wfh[idx] = h;
        g_Wfl[idx] = __float2bfloat16_rn(r);
    }
    if (idx < KQ * HQ) {
        int g = idx & (HQ - 1);
        int k = idx >> 8;
        g_WiT[idx] = Wi[g * KQ + k];
        g_WoT[idx] = Wo[g * KQ + k];
        g_WuT[idx] = Wu[g * KQ + k];
    }
    if (blockIdx.x == 0) {
        __shared__ int fl[2];
        int tid = threadIdx.x;
        if (tid < 2) fl[tid] = 0;
        if (tid < RQ) g_cnt[tid] = 0;
        __syncthreads();
        const unsigned char* mb = (const unsigned char*)vmask;
        for (int off = tid; off < 8192; off += 256) {
            int m = off & 3;
            unsigned char v = mb[off];
            if (m && v) {
                fl[0] = 1;                                     // non-aligned nonzero -> not i32
                if ((m == 2 && v == 0x80u) || (m == 3 && v == 0x3Fu))
                    fl[1] = 1;                                 // 1.0f byte pattern -> f32
            }
        }
        __syncthreads();
        if (tid == 0) g_mmode = fl[1] ? 2 : (fl[0] ? 1 : 0);   // 0=i32, 1=u8, 2=f32
    }
}

// -------- prep2: decay + counting-sort rows by relation --------
__global__ __launch_bounds__(256) void prep2_kernel(
    const int* __restrict__ rel_ids, const void* __restrict__ vmask)
{
    int i = blockIdx.x * 256 + threadIdx.x;
    if (i >= ROWS_TOT) return;
    int mmode = g_mmode;
    g_dec[i] = load_dec(vmask, i, mmode);
    int r = rel_ids[i];
    int pos = atomicAdd(&g_cnt[r], 1);
    g_idxr[r][pos] = i;
}

// -------- fgemm via mma.sync bf16 (2-term split, 3 products) --------
// Fragments staged in mma register order:
//  A m16k16 (4 regs/lane): reg = row_hi | (k_hi<<1); lane = (m&7)*4 + (kp&3)
//  B n8k16  (2 regs/lane): reg = kp>>2;              lane = (n&7)*4 + (kp&3)
extern __shared__ char smF[];

__global__ __launch_bounds__(256, 2) void fgemm_mma_kernel(
    const float* __restrict__ child_h)
{
    const int by = blockIdx.x;           // g tile (0..1)
    const int bx = blockIdx.y;           // row tile
    const int bz = blockIdx.z;           // relation
    const int cnt = g_cnt[bz];
    const int row0 = bx * TM;
    if (row0 >= cnt) return;

    int*      s_idx = (int*)smF;
    float*    s_dec = (float*)(smF + 512);
    uint32_t* frag  = (uint32_t*)(smF + 1024);

    const int tid  = threadIdx.x;
    const int lane = tid & 31;
    const int wid  = tid >> 5;
    const int wm   = wid >> 2;           // 0..1  (m half)
    const int wn   = wid & 3;            // 0..3  (n quarter)

    if (tid < TM) {
        int rr = row0 + tid;
        if (rr >= cnt) rr = cnt - 1;
        int gi = g_idxr[bz][rr];
        s_idx[tid] = gi;
        s_dec[tid] = g_dec[gi];
    }
    __syncthreads();

    float acc[4][4][4];
    #pragma unroll
    for (int a = 0; a < 4; a++)
        #pragma unroll
        for (int b = 0; b < 4; b++)
            #pragma unroll
            for (int c = 0; c < 4; c++) acc[a][b][c] = 0.0f;

    for (int kc = 0; kc < NCH; kc++) {
        // ---- stage A: gather rows, split fp32 -> bf16 hi/lo, fragment order ----
        #pragma unroll
        for (int it = 0; it < 8; it++) {
            int v  = tid + it * 256;       // 0..2047
            int m  = v >> 4;               // row 0..127
            int c4 = v & 15;               // float4 within 64-k chunk
            float4 a = *(const float4*)(child_h + (size_t)s_idx[m] * HQ + kc * KCH + c4 * 4);
            uint32_t h01 = pack_bf16x2(a.x, a.y);
            uint32_t h23 = pack_bf16x2(a.z, a.w);
            uint32_t l01 = pack_bf16x2(a.x - __bfloat162float(__float2bfloat16_rn(a.x)),
                                       a.y - __bfloat162float(__float2bfloat16_rn(a.y)));
            uint32_t l23 = pack_bf16x2(a.z - __bfloat162float(__float2bfloat16_rn(a.z)),
                                       a.w - __bfloat162float(__float2bfloat16_rn(a.w)));
            int tile_m = m >> 4, mr = m & 15;
            int kp0 = c4 * 2;              // pair index in chunk (0..31)
            #pragma unroll
            for (int s = 0; s < 2; s++) {
                int kp = kp0 + s;
                int tk = kp >> 3, pp = kp & 7;
                int ln = (mr & 7) * 4 + (pp & 3);
                int rg = ((mr >> 3) & 1) | ((pp >> 2) << 1);
                int off = ((tk * 8 + tile_m) * 32 + ln) * 4 + rg;
                frag[F_AH + off] = s ? h23 : h01;
                frag[F_AL + off] = s ? l23 : l01;
            }
        }
        // ---- stage B: pre-split weights (pairs already packed), fragment order ----
        #pragma unroll
        for (int it = 0; it < 4; it++) {
            int v = tid + it * 256;        // 0..1023
            int n = v >> 3;                // weight row (g), 0..127
            int c = v & 7;                 // uint4 (8 bf16) within 64-k chunk
            size_t src = ((size_t)(bz * HQ + by * TN + n)) * HQ + kc * KCH + c * 8;
            uint4 hv = *(const uint4*)(g_Wfh + src);
            uint4 lv = *(const uint4*)(g_Wfl + src);
            int tk = c >> 1, rg = c & 1, tn = n >> 3, nr = n & 7;
            int base = (tk * 16 + tn) * 32 + nr * 4;
            frag[F_BH + (base + 0) * 2 + rg] = hv.x;
            frag[F_BH + (base + 1) * 2 + rg] = hv.y;
            frag[F_BH + (base + 2) * 2 + rg] = hv.z;
            frag[F_BH + (base + 3) * 2 + rg] = hv.w;
            frag[F_BL + (base + 0) * 2 + rg] = lv.x;
            frag[F_BL + (base + 1) * 2 + rg] = lv.y;
            frag[F_BL + (base + 2) * 2 + rg] = lv.z;
            frag[F_BL + (base + 3) * 2 + rg] = lv.w;
        }
        __syncthreads();

        // ---- mma mainloop: 4 k16 steps, 3 products ----
        #pragma unroll
        for (int tk = 0; tk < 4; tk++) {
            uint32_t Ah[4][4], Al[4][4], Bh[4][2], Bl[4][2];
            #pragma unroll
            for (int tm = 0; tm < 4; tm++) {
                *(uint4*)Ah[tm] = *(const uint4*)&frag[F_AH + ((tk * 8 + wm * 4 + tm) * 32 + lane) * 4];
                *(uint4*)Al[tm] = *(const uint4*)&frag[F_AL + ((tk * 8 + wm * 4 + tm) * 32 + lane) * 4];
            }
            #pragma unroll
            for (int tn = 0; tn < 4; tn++) {
                *(uint2*)Bh[tn] = *(const uint2*)&frag[F_BH + ((tk * 16 + wn * 4 + tn) * 32 + lane) * 2];
                *(uint2*)Bl[tn] = *(const uint2*)&frag[F_BL + ((tk * 16 + wn * 4 + tn) * 32 + lane) * 2];
            }
            #pragma unroll
            for (int tm = 0; tm < 4; tm++)
                #pragma unroll
                for (int tn = 0; tn < 4; tn++) {
                    mma_bf16(acc[tm][tn], Ah[tm], Bh[tn]);
                    mma_bf16(acc[tm][tn], Ah[tm], Bl[tn]);
                    mma_bf16(acc[tm][tn], Al[tm], Bh[tn]);
                }
        }
        __syncthreads();
    }

    // ---- epilogue: scale by decay, scatter to g_f[row][g] ----
    const int qr = lane >> 2;
    const int qc = (lane & 3) * 2;
    #pragma unroll
    for (int tm = 0; tm < 4; tm++) {
        int m0 = wm * 64 + tm * 16 + qr;
        int m1 = m0 + 8;
        bool v0 = (row0 + m0) < cnt;
        bool v1 = (row0 + m1) < cnt;
        float d0 = s_dec[m0], d1 = s_dec[m1];
        float* dst0 = g_f + (size_t)s_idx[m0] * HQ + by * TN;
        float* dst1 = g_f + (size_t)s_idx[m1] * HQ + by * TN;
        #pragma unroll
        for (int tn = 0; tn < 4; tn++) {
            int col = (wn * 4 + tn) * 8 + qc;
            if (v0) *(float2*)(dst0 + col) = make_float2(acc[tm][tn][0] * d0, acc[tm][tn][1] * d0);
            if (v1) *(float2*)(dst1 + col) = make_float2(acc[tm][tn][2] * d1, acc[tm][tn][3] * d1);
        }
    }
}

// -------- combine: attention + child_h_sum + child_c_sum (R3 version) --------
__global__ __launch_bounds__(256) void combine_kernel(
    const float* __restrict__ child_h, const float* __restrict__ child_c,
    const int*   __restrict__ rel_ids, const float* __restrict__ rel_emb,
    const float* __restrict__ w_att,   const float* __restrict__ b_att,
    const float* __restrict__ b_f)
{
    __shared__ float sch[NQ][264];        // decayed child_h
    __shared__ float s_sc[32], s_dec[32];
    __shared__ int   s_rel[32];

    const int b = blockIdx.x, tid = threadIdx.x;
    const int warp = tid >> 5, lane = tid & 31;

    if (tid < NQ) {
        int i = b * NQ + tid;
        s_rel[tid] = rel_ids[i];
        s_dec[tid] = g_dec[i];
    }
    __syncthreads();

    {
        const float4* gh = (const float4*)(child_h + (size_t)b * NQ * HQ);
        #pragma unroll
        for (int k = 0; k < 8; k++) {
            int v  = tid + k * 256;
            int n  = v >> 6;
            int h4 = v & 63;
            float d = s_dec[n];
            float4 a = gh[v];
            a.x *= d; a.y *= d; a.z *= d; a.w *= d;
            *((float4*)&sch[n][h4 * 4]) = a;
        }
    }
    __syncthreads();

    {
        float batt = b_att[0];
        for (int nn = warp * 4; nn < warp * 4 + 4; nn++) {
            const float* rrow = rel_emb + s_rel[nn] * HQ;
            float p = 0.0f;
            #pragma unroll
            for (int h = lane; h < HQ; h += 32)
                p += (rrow[h] + sch[nn][h]) * w_att[h];
            #pragma unroll
            for (int o = 16; o; o >>= 1) p += __shfl_xor_sync(0xffffffffu, p, o);
            if (lane == 0) s_sc[nn] = p + batt;
        }
    }
    __syncthreads();

    if (warp == 0) {
        float s = s_sc[lane], m = s;
        #pragma unroll
        for (int o = 16; o; o >>= 1) m = fmaxf(m, __shfl_xor_sync(0xffffffffu, m, o));
        float e = __expf(s - m), su = e;
        #pragma unroll
        for (int o = 16; o; o >>= 1) su += __shfl_xor_sync(0xffffffffu, su, o);
        s_sc[lane] = e / su;
    }
    __syncthreads();

    {
        int g = tid;
        float bf0 = b_f[g], bf1 = b_f[HQ + g], bf2 = b_f[2 * HQ + g];
        const float* cc = child_c + (size_t)b * NQ * HQ + g;
        const float* ff = g_f + (size_t)b * NQ * HQ + g;
        float hacc = 0.0f, cacc = 0.0f;
        #pragma unroll 4
        for (int n = 0; n < NQ; n++) {
            hacc += s_sc[n] * sch[n][g];
            int rr = s_rel[n];
            float bf = (rr == 0) ? bf0 : ((rr == 1) ? bf1 : bf2);
            cacc += (ff[n * HQ] + bf) * (cc[n * HQ] * s_dec[n]);
        }
        g_hs[(size_t)b * HQ + g] = hacc;
        g_cs[(size_t)b * HQ + g] = cacc;
    }
}

// -------- gates GEMVs + pointwise epilogue (R3 version) --------
__global__ __launch_bounds__(256) void gates_kernel(
    const float* __restrict__ input_vec,
    const float* __restrict__ b_i, const float* __restrict__ b_o,
    const float* __restrict__ b_u, float* __restrict__ out)
{
    __shared__ float comb[MB][KQ];
    const int tid = threadIdx.x;
    const int b0  = blockIdx.x * MB;

    #pragma unroll
    for (int k = 0; k < MB * KQ / 4 / 256; k++) {
        int v  = tid + k * 256;
        int m  = v >> 7;
        int k4 = v & 127;
        int bb = b0 + m;
        float4 val;
        if (k4 < 64) val = ((const float4*)(input_vec + (size_t)bb * DINQ))[k4];
        else         val = ((const float4*)(g_hs      + (size_t)bb * HQ))[k4 - 64];
        *((float4*)&comb[m][k4 * 4]) = val;
    }
    __syncthreads();

    const int g = tid;
    float ai[MB], ao[MB], au[MB];
    #pragma unroll
    for (int m = 0; m < MB; m++) { ai[m] = 0.0f; ao[m] = 0.0f; au[m] = 0.0f; }

    const float* wi = g_WiT + g;
    const float* wo = g_WoT + g;
    const float* wu = g_WuT + g;

    #pragma unroll 4
    for (int k = 0; k < KQ; k++) {
        float vi = wi[(size_t)k * HQ];
        float vo = wo[(size_t)k * HQ];
        float vu = wu[(size_t)k * HQ];
        #pragma unroll
        for (int m = 0; m < MB; m++) {
            float cm = comb[m][k];
            ai[m] += cm * vi;
            ao[m] += cm * vo;
            au[m] += cm * vu;
        }
    }

    float bi = b_i[g], bo = b_o[g], bu = b_u[g];
    #pragma unroll
    for (int m = 0; m < MB; m++) {
        int bb = b0 + m;
        float iv = 1.0f / (1.0f + __expf(-(ai[m] + bi)));
        float ov = 1.0f / (1.0f + __expf(-(ao[m] + bo)));
        float uv = tanhf(au[m] + bu);
        float c  = iv * uv + g_cs[(size_t)bb * HQ + g];
        float h  = ov * tanhf(c);
        out[(size_t)bb * HQ + g]                   = h;
        out[(size_t)BQ * HQ + (size_t)bb * HQ + g] = c;
    }
}

// -------- launch --------
extern "C" void kernel_launch(void* const* d_in, const int* in_sizes, int n_in,
                              void* d_out, int out_size) {
    const float* input_vec = (const float*)d_in[0];
    const float* child_h   = (const float*)d_in[1];
    const float* child_c   = (const float*)d_in[2];
    const int*   rel_ids   = (const int*)  d_in[3];
    const void*  vmask     =               d_in[4];
    const float* rel_emb   = (const float*)d_in[5];
    const float* W_i       = (const float*)d_in[6];
    const float* b_i       = (const float*)d_in[7];
    const float* W_f       = (const float*)d_in[8];
    const float* b_f       = (const float*)d_in[9];
    const float* W_o       = (const float*)d_in[10];
    const float* b_o       = (const float*)d_in[11];
    const float* W_u       = (const float*)d_in[12];
    const float* b_u       = (const float*)d_in[13];
    const float* w_att     = (const float*)d_in[14];
    const float* b_att     = (const float*)d_in[15];
    float* out = (float*)d_out;

    prep1_kernel<<<(RQ * HQ * HQ + 255) / 256, 256>>>(W_f, W_i, W_o, W_u, vmask);
    prep2_kernel<<<ROWS_TOT / 256, 256>>>(rel_ids, vmask);

    cudaFuncSetAttribute(fgemm_mma_kernel,
                         cudaFuncAttributeMaxDynamicSharedMemorySize, FG_SMEM);
    dim3 ggrid(HQ / TN, ROWS_TOT / TM, RQ);   // (2, 1024, 3), early-exit on empty tiles
    fgemm_mma_kernel<<<ggrid, 256, FG_SMEM>>>(child_h);

    combine_kernel<<<BQ, 256>>>(child_h, child_c, rel_ids, rel_emb,
                                w_att, b_att, b_f);

    gates_kernel<<<BQ / MB, 256>>>(input_vec, b_i, b_o, b_u, out);
}

// round 8
// speedup vs baseline: 1.4164x; 1.0725x over previous
#include <cuda_runtime.h>
#include <cuda_bf16.h>
#include <cstdint>

// Problem constants
#define BQ   4096
#define NQ   32
#define HQ   256
#define DINQ 256
#define RQ   3
#define KQ   (DINQ + HQ)   // 512
#define VIRTUAL_DECAY 0.7f
#define MB   16            // batches per CTA in gate kernel
#define ROWS_TOT (BQ * NQ) // 131072

// mma fgemm tiling
#define TM 128             // rows per CTA tile
#define TN 128             // g per CTA tile
#define KCH 64             // k per staged chunk
#define NCH (HQ / KCH)     // 4 chunks
#define ASTRD 72           // smem row stride in bf16 (144B: 16B-aligned, conflict-free)

// smem byte offsets
#define SMO_IDX 0
#define SMO_DEC 512
#define SMO_AH  1024
#define SMO_AL  (SMO_AH + TM * ASTRD * 2)   // +18432
#define SMO_BH  (SMO_AL + TM * ASTRD * 2)
#define SMO_BL  (SMO_BH + TN * ASTRD * 2)
#define FG_SMEM (SMO_BL + TN * ASTRD * 2)   // 74752 bytes

// -------- device scratch (no dynamic allocation allowed) --------
__device__ __nv_bfloat16 g_Wfh[RQ * HQ * HQ];  // W_f split, [r][g][h]
__device__ __nv_bfloat16 g_Wfl[RQ * HQ * HQ];
__device__ float g_WiT[KQ * HQ];        // [k][g]
__device__ float g_WoT[KQ * HQ];
__device__ float g_WuT[KQ * HQ];
__device__ float g_hs[BQ * HQ];         // child_h_sum
__device__ float g_cs[BQ * HQ];         // child_c_sum
__device__ float g_f[(size_t)ROWS_TOT * HQ];   // f gate results, [b][n][g]
__device__ float g_dec[ROWS_TOT];       // decay per row
__device__ int   g_idxr[RQ][ROWS_TOT];  // row indices grouped by relation
__device__ int   g_cnt[RQ];
__device__ int   g_mmode;               // virtual_mask storage dtype

__device__ __forceinline__ uint32_t pack_bf16x2(float x, float y) {
    __nv_bfloat16 a = __float2bfloat16_rn(x);
    __nv_bfloat16 b = __float2bfloat16_rn(y);
    return (uint32_t)__bfloat16_as_ushort(a) | ((uint32_t)__bfloat16_as_ushort(b) << 16);
}
__device__ __forceinline__ void mma_bf16(float* c, const uint32_t* a, const uint32_t* b) {
    asm volatile(
        "mma.sync.aligned.m16n8k16.row.col.f32.bf16.bf16.f32 "
        "{%0,%1,%2,%3}, {%4,%5,%6,%7}, {%8,%9}, {%0,%1,%2,%3};"
        : "+f"(c[0]), "+f"(c[1]), "+f"(c[2]), "+f"(c[3])
        : "r"(a[0]), "r"(a[1]), "r"(a[2]), "r"(a[3]), "r"(b[0]), "r"(b[1]));
}
__device__ __forceinline__ void ldsm_x4(uint32_t* r, uint32_t addr) {
    asm volatile("ldmatrix.sync.aligned.m8n8.x4.shared.b16 {%0,%1,%2,%3}, [%4];"
                 : "=r"(r[0]), "=r"(r[1]), "=r"(r[2]), "=r"(r[3]) : "r"(addr));
}

__device__ __forceinline__ float load_dec(const void* vmask, int i, int mmode) {
    bool mv;
    if (mmode == 0)      mv = ((const int*)vmask)[i] != 0;
    else if (mmode == 1) mv = ((const unsigned char*)vmask)[i] != 0;
    else                 mv = ((const float*)vmask)[i] != 0.0f;
    return mv ? VIRTUAL_DECAY : 1.0f;
}

// -------- prep1: weight split + gate transposes + mask dtype + zero counters --------
__global__ __launch_bounds__(256) void prep1_kernel(
    const float* __restrict__ Wf, const float* __restrict__ Wi,
    const float* __restrict__ Wo, const float* __restrict__ Wu,
    const void* __restrict__ vmask)
{
    int idx = blockIdx.x * 256 + threadIdx.x;
    if (idx < RQ * HQ * HQ) {
        float x = Wf[idx];
        __nv_bfloat16 h = __float2bfloat16_rn(x);
        float r = x - __bfloat162float(h);
        g_Wfh[idx] = h;
        g_Wfl[idx] = __float2bfloat16_rn(r);
    }
    if (idx < KQ * HQ) {
        int g = idx & (HQ - 1);
        int k = idx >> 8;
        g_WiT[idx] = Wi[g * KQ + k];
        g_WoT[idx] = Wo[g * KQ + k];
        g_WuT[idx] = Wu[g * KQ + k];
    }
    if (blockIdx.x == 0) {
        __shared__ int fl[2];
        int tid = threadIdx.x;
        if (tid < 2) fl[tid] = 0;
        if (tid < RQ) g_cnt[tid] = 0;
        __syncthreads();
        const unsigned char* mb = (const unsigned char*)vmask;
        for (int off = tid; off < 8192; off += 256) {
            int m = off & 3;
            unsigned char v = mb[off];
            if (m && v) {
                fl[0] = 1;                                     // non-aligned nonzero -> not i32
                if ((m == 2 && v == 0x80u) || (m == 3 && v == 0x3Fu))
                    fl[1] = 1;                                 // 1.0f byte pattern -> f32
            }
        }
        __syncthreads();
        if (tid == 0) g_mmode = fl[1] ? 2 : (fl[0] ? 1 : 0);   // 0=i32, 1=u8, 2=f32
    }
}

// -------- prep2: decay + counting-sort rows by relation --------
__global__ __launch_bounds__(256) void prep2_kernel(
    const int* __restrict__ rel_ids, const void* __restrict__ vmask)
{
    int i = blockIdx.x * 256 + threadIdx.x;
    if (i >= ROWS_TOT) return;
    int mmode = g_mmode;
    g_dec[i] = load_dec(vmask, i, mmode);
    int r = rel_ids[i];
    int pos = atomicAdd(&g_cnt[r], 1);
    g_idxr[r][pos] = i;
}

// -------- fgemm via mma.sync bf16 (2-term split, 3 products), ldmatrix path --------
extern __shared__ char smF[];

__global__ __launch_bounds__(256, 1) void fgemm_mma_kernel(
    const float* __restrict__ child_h)
{
    const int by = blockIdx.x;           // g tile (0..1)
    const int bx = blockIdx.y;           // row tile
    const int bz = blockIdx.z;           // relation
    const int cnt = g_cnt[bz];
    const int row0 = bx * TM;
    if (row0 >= cnt) return;

    int*   s_idx = (int*)(smF + SMO_IDX);
    float* s_dec = (float*)(smF + SMO_DEC);

    const int tid  = threadIdx.x;
    const int lane = tid & 31;
    const int wid  = tid >> 5;
    const int wm   = wid >> 2;           // 0..1  (m half)
    const int wn   = wid & 3;            // 0..3  (n quarter, 32 g each)

    const uint32_t smem_base = (uint32_t)__cvta_generic_to_shared(smF);

    if (tid < TM) {
        int rr = row0 + tid;
        if (rr >= cnt) rr = cnt - 1;
        int gi = g_idxr[bz][rr];
        s_idx[tid] = gi;
        s_dec[tid] = g_dec[gi];
    }
    __syncthreads();

    // per-thread staging coordinates
    const int am = tid >> 4;             // A: row 0..127 (wait: 2048 float4 / 256 = 8 iters)
    // prefetch registers
    float4 aPref[8];
    uint4  bhPref[4], blPref[4];

    auto ldA = [&](int kc) {
        #pragma unroll
        for (int it = 0; it < 8; it++) {
            int v  = tid + it * 256;     // 0..2047
            int m  = v >> 4;             // row
            int c4 = v & 15;             // float4 within 64-k chunk
            aPref[it] = *(const float4*)(child_h + (size_t)s_idx[m] * HQ + kc * KCH + c4 * 4);
        }
    };
    auto ldB = [&](int kc) {
        #pragma unroll
        for (int it = 0; it < 4; it++) {
            int v = tid + it * 256;      // 0..1023
            int n = v >> 3;              // g row 0..127
            int c = v & 7;               // uint4 (8 bf16) within 64-k chunk
            size_t src = ((size_t)(bz * HQ + by * TN + n)) * HQ + kc * KCH + c * 8;
            bhPref[it] = *(const uint4*)(g_Wfh + src);
            blPref[it] = *(const uint4*)(g_Wfl + src);
        }
    };
    auto stAB = [&]() {
        #pragma unroll
        for (int it = 0; it < 8; it++) {
            int v  = tid + it * 256;
            int m  = v >> 4;
            int c4 = v & 15;
            float4 a = aPref[it];
            uint32_t h01 = pack_bf16x2(a.x, a.y);
            uint32_t h23 = pack_bf16x2(a.z, a.w);
            uint32_t l01 = pack_bf16x2(a.x - __bfloat162float(__float2bfloat16_rn(a.x)),
                                       a.y - __bfloat162float(__float2bfloat16_rn(a.y)));
            uint32_t l23 = pack_bf16x2(a.z - __bfloat162float(__float2bfloat16_rn(a.z)),
                                       a.w - __bfloat162float(__float2bfloat16_rn(a.w)));
            int off = m * (ASTRD * 2) + c4 * 8;
            *(uint2*)(smF + SMO_AH + off) = make_uint2(h01, h23);
            *(uint2*)(smF + SMO_AL + off) = make_uint2(l01, l23);
        }
        #pragma unroll
        for (int it = 0; it < 4; it++) {
            int v = tid + it * 256;
            int n = v >> 3;
            int c = v & 7;
            int off = n * (ASTRD * 2) + c * 16;
            *(uint4*)(smF + SMO_BH + off) = bhPref[it];
            *(uint4*)(smF + SMO_BL + off) = blPref[it];
        }
    };

    float acc[4][4][4];
    #pragma unroll
    for (int a = 0; a < 4; a++)
        #pragma unroll
        for (int b = 0; b < 4; b++)
            #pragma unroll
            for (int c = 0; c < 4; c++) acc[a][b][c] = 0.0f;

    // ldmatrix lane address components
    const int arow  = lane & 15;             // + m0
    const int acol8 = (lane >> 4) << 3;      // k offset 0/8
    const int brow  = (lane & 7) + ((lane >> 4) << 3);   // + n0
    const int bcol8 = ((lane >> 3) & 1) << 3;

    ldA(0); ldB(0);

    for (int kc = 0; kc < NCH; kc++) {
        stAB();
        __syncthreads();
        if (kc + 1 < NCH) { ldA(kc + 1); ldB(kc + 1); }

        #pragma unroll
        for (int tk = 0; tk < 4; tk++) {
            const int k0 = tk * 16;
            uint32_t Ah[4][4], Al[4][4], Bh[4][2], Bl[4][2];
            #pragma unroll
            for (int tm = 0; tm < 4; tm++) {
                int r = wm * 64 + tm * 16 + arow;
                uint32_t ao = smem_base + SMO_AH + (uint32_t)(r * (ASTRD * 2) + (k0 + acol8) * 2);
                uint32_t lo = ao + (SMO_AL - SMO_AH);
                ldsm_x4(Ah[tm], ao);
                ldsm_x4(Al[tm], lo);
            }
            #pragma unroll
            for (int p = 0; p < 2; p++) {
                int r = wn * 32 + p * 16 + brow;
                uint32_t bo = smem_base + SMO_BH + (uint32_t)(r * (ASTRD * 2) + (k0 + bcol8) * 2);
                uint32_t lo = bo + (SMO_BL - SMO_BH);
                uint32_t tmpH[4], tmpL[4];
                ldsm_x4(tmpH, bo);
                ldsm_x4(tmpL, lo);
                Bh[2 * p][0] = tmpH[0]; Bh[2 * p][1] = tmpH[1];
                Bh[2 * p + 1][0] = tmpH[2]; Bh[2 * p + 1][1] = tmpH[3];
                Bl[2 * p][0] = tmpL[0]; Bl[2 * p][1] = tmpL[1];
                Bl[2 * p + 1][0] = tmpL[2]; Bl[2 * p + 1][1] = tmpL[3];
            }
            #pragma unroll
            for (int tm = 0; tm < 4; tm++)
                #pragma unroll
                for (int tn = 0; tn < 4; tn++) {
                    mma_bf16(acc[tm][tn], Ah[tm], Bh[tn]);
                    mma_bf16(acc[tm][tn], Ah[tm], Bl[tn]);
                    mma_bf16(acc[tm][tn], Al[tm], Bh[tn]);
                }
        }
        __syncthreads();
    }

    // ---- epilogue: scale by decay, scatter to g_f[row][g] ----
    const int qr = lane >> 2;
    const int qc = (lane & 3) * 2;
    #pragma unroll
    for (int tm = 0; tm < 4; tm++) {
        int m0 = wm * 64 + tm * 16 + qr;
        int m1 = m0 + 8;
        bool v0 = (row0 + m0) < cnt;
        bool v1 = (row0 + m1) < cnt;
        float d0 = s_dec[m0], d1 = s_dec[m1];
        float* dst0 = g_f + (size_t)s_idx[m0] * HQ + by * TN;
        float* dst1 = g_f + (size_t)s_idx[m1] * HQ + by * TN;
        #pragma unroll
        for (int tn = 0; tn < 4; tn++) {
            int col = (wn * 4 + tn) * 8 + qc;
            if (v0) *(float2*)(dst0 + col) = make_float2(acc[tm][tn][0] * d0, acc[tm][tn][1] * d0);
            if (v1) *(float2*)(dst1 + col) = make_float2(acc[tm][tn][2] * d1, acc[tm][tn][3] * d1);
        }
    }
}

// -------- combine: attention + child_h_sum + child_c_sum --------
__global__ __launch_bounds__(256) void combine_kernel(
    const float* __restrict__ child_h, const float* __restrict__ child_c,
    const int*   __restrict__ rel_ids, const float* __restrict__ rel_emb,
    const float* __restrict__ w_att,   const float* __restrict__ b_att,
    const float* __restrict__ b_f)
{
    __shared__ float sch[NQ][264];        // decayed child_h
    __shared__ float s_sc[32], s_dec[32];
    __shared__ int   s_rel[32];

    const int b = blockIdx.x, tid = threadIdx.x;
    const int warp = tid >> 5, lane = tid & 31;

    if (tid < NQ) {
        int i = b * NQ + tid;
        s_rel[tid] = rel_ids[i];
        s_dec[tid] = g_dec[i];
    }
    __syncthreads();

    {
        const float4* gh = (const float4*)(child_h + (size_t)b * NQ * HQ);
        #pragma unroll
        for (int k = 0; k < 8; k++) {
            int v  = tid + k * 256;
            int n  = v >> 6;
            int h4 = v & 63;
            float d = s_dec[n];
            float4 a = gh[v];
            a.x *= d; a.y *= d; a.z *= d; a.w *= d;
            *((float4*)&sch[n][h4 * 4]) = a;
        }
    }
    __syncthreads();

    {
        float batt = b_att[0];
        for (int nn = warp * 4; nn < warp * 4 + 4; nn++) {
            const float* rrow = rel_emb + s_rel[nn] * HQ;
            float p = 0.0f;
            #pragma unroll
            for (int h = lane; h < HQ; h += 32)
                p += (rrow[h] + sch[nn][h]) * w_att[h];
            #pragma unroll
            for (int o = 16; o; o >>= 1) p += __shfl_xor_sync(0xffffffffu, p, o);
            if (lane == 0) s_sc[nn] = p + batt;
        }
    }
    __syncthreads();

    if (warp == 0) {
        float s = s_sc[lane], m = s;
        #pragma unroll
        for (int o = 16; o; o >>= 1) m = fmaxf(m, __shfl_xor_sync(0xffffffffu, m, o));
        float e = __expf(s - m), su = e;
        #pragma unroll
        for (int o = 16; o; o >>= 1) su += __shfl_xor_sync(0xffffffffu, su, o);
        s_sc[lane] = e / su;
    }
    __syncthreads();

    {
        int g = tid;
        float bf0 = b_f[g], bf1 = b_f[HQ + g], bf2 = b_f[2 * HQ + g];
        const float* cc = child_c + (size_t)b * NQ * HQ + g;
        const float* ff = g_f + (size_t)b * NQ * HQ + g;
        float hacc = 0.0f, cacc = 0.0f;
        #pragma unroll 4
        for (int n = 0; n < NQ; n++) {
            hacc += s_sc[n] * sch[n][g];
            int rr = s_rel[n];
            float bf = (rr == 0) ? bf0 : ((rr == 1) ? bf1 : bf2);
            cacc += (ff[n * HQ] + bf) * (cc[n * HQ] * s_dec[n]);
        }
        g_hs[(size_t)b * HQ + g] = hacc;
        g_cs[(size_t)b * HQ + g] = cacc;
    }
}

// -------- gates GEMVs + pointwise epilogue --------
__global__ __launch_bounds__(256) void gates_kernel(
    const float* __restrict__ input_vec,
    const float* __restrict__ b_i, const float* __restrict__ b_o,
    const float* __restrict__ b_u, float* __restrict__ out)
{
    __shared__ float comb[MB][KQ];
    const int tid = threadIdx.x;
    const int b0  = blockIdx.x * MB;

    #pragma unroll
    for (int k = 0; k < MB * KQ / 4 / 256; k++) {
        int v  = tid + k * 256;
        int m  = v >> 7;
        int k4 = v & 127;
        int bb = b0 + m;
        float4 val;
        if (k4 < 64) val = ((const float4*)(input_vec + (size_t)bb * DINQ))[k4];
        else         val = ((const float4*)(g_hs      + (size_t)bb * HQ))[k4 - 64];
        *((float4*)&comb[m][k4 * 4]) = val;
    }
    __syncthreads();

    const int g = tid;
    float ai[MB], ao[MB], au[MB];
    #pragma unroll
    for (int m = 0; m < MB; m++) { ai[m] = 0.0f; ao[m] = 0.0f; au[m] = 0.0f; }

    const float* wi = g_WiT + g;
    const float* wo = g_WoT + g;
    const float* wu = g_WuT + g;

    #pragma unroll 4
    for (int k = 0; k < KQ; k++) {
        float vi = wi[(size_t)k * HQ];
        float vo = wo[(size_t)k * HQ];
        float vu = wu[(size_t)k * HQ];
        #pragma unroll
        for (int m = 0; m < MB; m++) {
            float cm = comb[m][k];
            ai[m] += cm * vi;
            ao[m] += cm * vo;
            au[m] += cm * vu;
        }
    }

    float bi = b_i[g], bo = b_o[g], bu = b_u[g];
    #pragma unroll
    for (int m = 0; m < MB; m++) {
        int bb = b0 + m;
        float iv = 1.0f / (1.0f + __expf(-(ai[m] + bi)));
        float ov = 1.0f / (1.0f + __expf(-(ao[m] + bo)));
        float uv = tanhf(au[m] + bu);
        float c  = iv * uv + g_cs[(size_t)bb * HQ + g];
        float h  = ov * tanhf(c);
        out[(size_t)bb * HQ + g]                   = h;
        out[(size_t)BQ * HQ + (size_t)bb * HQ + g] = c;
    }
}

// -------- launch --------
extern "C" void kernel_launch(void* const* d_in, const int* in_sizes, int n_in,
                              void* d_out, int out_size) {
    const float* input_vec = (const float*)d_in[0];
    const float* child_h   = (const float*)d_in[1];
    const float* child_c   = (const float*)d_in[2];
    const int*   rel_ids   = (const int*)  d_in[3];
    const void*  vmask     =               d_in[4];
    const float* rel_emb   = (const float*)d_in[5];
    const float* W_i       = (const float*)d_in[6];
    const float* b_i       = (const float*)d_in[7];
    const float* W_f       = (const float*)d_in[8];
    const float* b_f       = (const float*)d_in[9];
    const float* W_o       = (const float*)d_in[10];
    const float* b_o       = (const float*)d_in[11];
    const float* W_u       = (const float*)d_in[12];
    const float* b_u       = (const float*)d_in[13];
    const float* w_att     = (const float*)d_in[14];
    const float* b_att     = (const float*)d_in[15];
    float* out = (float*)d_out;

    prep1_kernel<<<(RQ * HQ * HQ + 255) / 256, 256>>>(W_f, W_i, W_o, W_u, vmask);
    prep2_kernel<<<ROWS_TOT / 256, 256>>>(rel_ids, vmask);

    cudaFuncSetAttribute(fgemm_mma_kernel,
                         cudaFuncAttributeMaxDynamicSharedMemorySize, FG_SMEM);
    dim3 ggrid(HQ / TN, ROWS_TOT / TM, RQ);   // (2, 1024, 3), early-exit on empty tiles
    fgemm_mma_kernel<<<ggrid, 256, FG_SMEM>>>(child_h);

    combine_kernel<<<BQ, 256>>>(child_h, child_c, rel_ids, rel_emb,
                                w_att, b_att, b_f);

    gates_kernel<<<BQ / MB, 256>>>(input_vec, b_i, b_o, b_u, out);
}

// round 9
// speedup vs baseline: 1.7383x; 1.2272x over previous
#include <cuda_runtime.h>
#include <cuda_bf16.h>
#include <cstdint>

// Problem constants
#define BQ   4096
#define NQ   32
#define HQ   256
#define DINQ 256
#define RQ   3
#define KQ   (DINQ + HQ)   // 512
#define VIRTUAL_DECAY 0.7f
#define MB   32            // batches per CTA in gate kernel
#define ROWS_TOT (BQ * NQ) // 131072

// mma fgemm tiling
#define TM 128             // rows per CTA tile
#define TN 128             // g per CTA tile
#define KCH 64             // k per staged chunk
#define NCH (HQ / KCH)     // 4 chunks
#define ASTRD 72           // smem row stride in bf16 (144B: 16B-aligned, conflict-free)

// smem byte offsets (fgemm)
#define SMO_IDX 0
#define SMO_DEC 512
#define SMO_AH  1024
#define SMO_AL  (SMO_AH + TM * ASTRD * 2)   // +18432
#define SMO_BH  (SMO_AL + TM * ASTRD * 2)
#define SMO_BL  (SMO_BH + TN * ASTRD * 2)
#define FG_SMEM (SMO_BL + TN * ASTRD * 2)   // 74752 bytes

#define GATES_SMEM (MB * KQ * 4)            // 65536 bytes

// -------- device scratch (no dynamic allocation allowed) --------
__device__ __nv_bfloat16 g_Wfh[RQ * HQ * HQ];  // W_f split, [r][g][h]
__device__ __nv_bfloat16 g_Wfl[RQ * HQ * HQ];
__device__ float g_WiT[KQ * HQ];        // [k][g]
__device__ float g_WoT[KQ * HQ];
__device__ float g_WuT[KQ * HQ];
__device__ float g_hs[BQ * HQ];         // child_h_sum
__device__ float g_cs[BQ * HQ];         // child_c_sum
__device__ float g_f[(size_t)ROWS_TOT * HQ];   // f gate results, [b][n][g]
__device__ float g_dec[ROWS_TOT];       // decay per row
__device__ int   g_idxr[RQ][ROWS_TOT];  // row indices grouped by relation
__device__ int   g_cnt[RQ];
__device__ int   g_mmode;               // virtual_mask storage dtype

__device__ __forceinline__ uint32_t pack_bf16x2(float x, float y) {
    __nv_bfloat16 a = __float2bfloat16_rn(x);
    __nv_bfloat16 b = __float2bfloat16_rn(y);
    return (uint32_t)__bfloat16_as_ushort(a) | ((uint32_t)__bfloat16_as_ushort(b) << 16);
}
__device__ __forceinline__ void mma_bf16(float* c, const uint32_t* a, const uint32_t* b) {
    asm volatile(
        "mma.sync.aligned.m16n8k16.row.col.f32.bf16.bf16.f32 "
        "{%0,%1,%2,%3}, {%4,%5,%6,%7}, {%8,%9}, {%0,%1,%2,%3};"
        : "+f"(c[0]), "+f"(c[1]), "+f"(c[2]), "+f"(c[3])
        : "r"(a[0]), "r"(a[1]), "r"(a[2]), "r"(a[3]), "r"(b[0]), "r"(b[1]));
}
__device__ __forceinline__ void ldsm_x4(uint32_t* r, uint32_t addr) {
    asm volatile("ldmatrix.sync.aligned.m8n8.x4.shared.b16 {%0,%1,%2,%3}, [%4];"
                 : "=r"(r[0]), "=r"(r[1]), "=r"(r[2]), "=r"(r[3]) : "r"(addr));
}

__device__ __forceinline__ float load_dec(const void* vmask, int i, int mmode) {
    bool mv;
    if (mmode == 0)      mv = ((const int*)vmask)[i] != 0;
    else if (mmode == 1) mv = ((const unsigned char*)vmask)[i] != 0;
    else                 mv = ((const float*)vmask)[i] != 0.0f;
    return mv ? VIRTUAL_DECAY : 1.0f;
}

// -------- prep1: weight split + gate transposes + mask dtype + zero counters --------
__global__ __launch_bounds__(256) void prep1_kernel(
    const float* __restrict__ Wf, const float* __restrict__ Wi,
    const float* __restrict__ Wo, const float* __restrict__ Wu,
    const void* __restrict__ vmask)
{
    int idx = blockIdx.x * 256 + threadIdx.x;
    if (idx < RQ * HQ * HQ) {
        float x = Wf[idx];
        __nv_bfloat16 h = __float2bfloat16_rn(x);
        float r = x - __bfloat162float(h);
        g_Wfh[idx] = h;
        g_Wfl[idx] = __float2bfloat16_rn(r);
    }
    if (idx < KQ * HQ) {
        int g = idx & (HQ - 1);
        int k = idx >> 8;
        g_WiT[idx] = Wi[g * KQ + k];
        g_WoT[idx] = Wo[g * KQ + k];
        g_WuT[idx] = Wu[g * KQ + k];
    }
    if (blockIdx.x == 0) {
        __shared__ int fl[2];
        int tid = threadIdx.x;
        if (tid < 2) fl[tid] = 0;
        if (tid < RQ) g_cnt[tid] = 0;
        __syncthreads();
        const unsigned char* mb = (const unsigned char*)vmask;
        for (int off = tid; off < 8192; off += 256) {
            int m = off & 3;
            unsigned char v = mb[off];
            if (m && v) {
                fl[0] = 1;                                     // non-aligned nonzero -> not i32
                if ((m == 2 && v == 0x80u) || (m == 3 && v == 0x3Fu))
                    fl[1] = 1;                                 // 1.0f byte pattern -> f32
            }
        }
        __syncthreads();
        if (tid == 0) g_mmode = fl[1] ? 2 : (fl[0] ? 1 : 0);   // 0=i32, 1=u8, 2=f32
    }
}

// -------- prep2: decay + counting-sort rows by relation --------
__global__ __launch_bounds__(256) void prep2_kernel(
    const int* __restrict__ rel_ids, const void* __restrict__ vmask)
{
    int i = blockIdx.x * 256 + threadIdx.x;
    if (i >= ROWS_TOT) return;
    int mmode = g_mmode;
    g_dec[i] = load_dec(vmask, i, mmode);
    int r = rel_ids[i];
    int pos = atomicAdd(&g_cnt[r], 1);
    g_idxr[r][pos] = i;
}

// -------- attn: attention + child_h_sum (independent of fgemm) --------
__global__ __launch_bounds__(256) void attn_kernel(
    const float* __restrict__ child_h, const int* __restrict__ rel_ids,
    const float* __restrict__ rel_emb, const float* __restrict__ w_att,
    const float* __restrict__ b_att)
{
    __shared__ float sch[NQ][264];        // decayed child_h
    __shared__ float s_sc[32], s_dec[32];
    __shared__ int   s_rel[32];

    const int b = blockIdx.x, tid = threadIdx.x;
    const int warp = tid >> 5, lane = tid & 31;

    if (tid < NQ) {
        int i = b * NQ + tid;
        s_rel[tid] = rel_ids[i];
        s_dec[tid] = g_dec[i];
    }
    __syncthreads();

    {
        const float4* gh = (const float4*)(child_h + (size_t)b * NQ * HQ);
        #pragma unroll
        for (int k = 0; k < 8; k++) {
            int v  = tid + k * 256;
            int n  = v >> 6;
            int h4 = v & 63;
            float d = s_dec[n];
            float4 a = gh[v];
            a.x *= d; a.y *= d; a.z *= d; a.w *= d;
            *((float4*)&sch[n][h4 * 4]) = a;
        }
    }
    __syncthreads();

    {
        float batt = b_att[0];
        for (int nn = warp * 4; nn < warp * 4 + 4; nn++) {
            const float* rrow = rel_emb + s_rel[nn] * HQ;
            float p = 0.0f;
            #pragma unroll
            for (int h = lane; h < HQ; h += 32)
                p += (rrow[h] + sch[nn][h]) * w_att[h];
            #pragma unroll
            for (int o = 16; o; o >>= 1) p += __shfl_xor_sync(0xffffffffu, p, o);
            if (lane == 0) s_sc[nn] = p + batt;
        }
    }
    __syncthreads();

    if (warp == 0) {
        float s = s_sc[lane], m = s;
        #pragma unroll
        for (int o = 16; o; o >>= 1) m = fmaxf(m, __shfl_xor_sync(0xffffffffu, m, o));
        float e = __expf(s - m), su = e;
        #pragma unroll
        for (int o = 16; o; o >>= 1) su += __shfl_xor_sync(0xffffffffu, su, o);
        s_sc[lane] = e / su;
    }
    __syncthreads();

    {
        int g = tid;
        float acc = 0.0f;
        #pragma unroll
        for (int n = 0; n < NQ; n++)
            acc += s_sc[n] * sch[n][g];
        g_hs[(size_t)b * HQ + g] = acc;
    }
}

// -------- fgemm via mma.sync bf16 (2-term split, 3 products), ldmatrix path --------
extern __shared__ char smF[];

__global__ __launch_bounds__(256, 1) void fgemm_mma_kernel(
    const float* __restrict__ child_h)
{
    const int by = blockIdx.x;           // g tile (0..1)
    const int bx = blockIdx.y;           // row tile
    const int bz = blockIdx.z;           // relation
    const int cnt = g_cnt[bz];
    const int row0 = bx * TM;
    if (row0 >= cnt) return;

    int*   s_idx = (int*)(smF + SMO_IDX);
    float* s_dec = (float*)(smF + SMO_DEC);

    const int tid  = threadIdx.x;
    const int lane = tid & 31;
    const int wid  = tid >> 5;
    const int wm   = wid >> 2;           // 0..1  (m half)
    const int wn   = wid & 3;            // 0..3  (n quarter, 32 g each)

    const uint32_t smem_base = (uint32_t)__cvta_generic_to_shared(smF);

    if (tid < TM) {
        int rr = row0 + tid;
        if (rr >= cnt) rr = cnt - 1;
        int gi = g_idxr[bz][rr];
        s_idx[tid] = gi;
        s_dec[tid] = g_dec[gi];
    }
    __syncthreads();

    float4 aPref[8];
    uint4  bhPref[4], blPref[4];

    auto ldA = [&](int kc) {
        #pragma unroll
        for (int it = 0; it < 8; it++) {
            int v  = tid + it * 256;     // 0..2047
            int m  = v >> 4;             // row
            int c4 = v & 15;             // float4 within 64-k chunk
            aPref[it] = *(const float4*)(child_h + (size_t)s_idx[m] * HQ + kc * KCH + c4 * 4);
        }
    };
    auto ldB = [&](int kc) {
        #pragma unroll
        for (int it = 0; it < 4; it++) {
            int v = tid + it * 256;      // 0..1023
            int n = v >> 3;              // g row 0..127
            int c = v & 7;               // uint4 (8 bf16) within 64-k chunk
            size_t src = ((size_t)(bz * HQ + by * TN + n)) * HQ + kc * KCH + c * 8;
            bhPref[it] = *(const uint4*)(g_Wfh + src);
            blPref[it] = *(const uint4*)(g_Wfl + src);
        }
    };
    auto stAB = [&]() {
        #pragma unroll
        for (int it = 0; it < 8; it++) {
            int v  = tid + it * 256;
            int m  = v >> 4;
            int c4 = v & 15;
            float4 a = aPref[it];
            uint32_t h01 = pack_bf16x2(a.x, a.y);
            uint32_t h23 = pack_bf16x2(a.z, a.w);
            uint32_t l01 = pack_bf16x2(a.x - __bfloat162float(__float2bfloat16_rn(a.x)),
                                       a.y - __bfloat162float(__float2bfloat16_rn(a.y)));
            uint32_t l23 = pack_bf16x2(a.z - __bfloat162float(__float2bfloat16_rn(a.z)),
                                       a.w - __bfloat162float(__float2bfloat16_rn(a.w)));
            int off = m * (ASTRD * 2) + c4 * 8;
            *(uint2*)(smF + SMO_AH + off) = make_uint2(h01, h23);
            *(uint2*)(smF + SMO_AL + off) = make_uint2(l01, l23);
        }
        #pragma unroll
        for (int it = 0; it < 4; it++) {
            int v = tid + it * 256;
            int n = v >> 3;
            int c = v & 7;
            int off = n * (ASTRD * 2) + c * 16;
            *(uint4*)(smF + SMO_BH + off) = bhPref[it];
            *(uint4*)(smF + SMO_BL + off) = blPref[it];
        }
    };

    float acc[4][4][4];
    #pragma unroll
    for (int a = 0; a < 4; a++)
        #pragma unroll
        for (int b = 0; b < 4; b++)
            #pragma unroll
            for (int c = 0; c < 4; c++) acc[a][b][c] = 0.0f;

    const int arow  = lane & 15;
    const int acol8 = (lane >> 4) << 3;
    const int brow  = (lane & 7) + ((lane >> 4) << 3);
    const int bcol8 = ((lane >> 3) & 1) << 3;

    ldA(0); ldB(0);

    for (int kc = 0; kc < NCH; kc++) {
        stAB();
        __syncthreads();
        if (kc + 1 < NCH) { ldA(kc + 1); ldB(kc + 1); }

        #pragma unroll
        for (int tk = 0; tk < 4; tk++) {
            const int k0 = tk * 16;
            uint32_t Ah[4][4], Al[4][4], Bh[4][2], Bl[4][2];
            #pragma unroll
            for (int tm = 0; tm < 4; tm++) {
                int r = wm * 64 + tm * 16 + arow;
                uint32_t ao = smem_base + SMO_AH + (uint32_t)(r * (ASTRD * 2) + (k0 + acol8) * 2);
                uint32_t lo = ao + (SMO_AL - SMO_AH);
                ldsm_x4(Ah[tm], ao);
                ldsm_x4(Al[tm], lo);
            }
            #pragma unroll
            for (int p = 0; p < 2; p++) {
                int r = wn * 32 + p * 16 + brow;
                uint32_t bo = smem_base + SMO_BH + (uint32_t)(r * (ASTRD * 2) + (k0 + bcol8) * 2);
                uint32_t lo = bo + (SMO_BL - SMO_BH);
                uint32_t tmpH[4], tmpL[4];
                ldsm_x4(tmpH, bo);
                ldsm_x4(tmpL, lo);
                Bh[2 * p][0] = tmpH[0]; Bh[2 * p][1] = tmpH[1];
                Bh[2 * p + 1][0] = tmpH[2]; Bh[2 * p + 1][1] = tmpH[3];
                Bl[2 * p][0] = tmpL[0]; Bl[2 * p][1] = tmpL[1];
                Bl[2 * p + 1][0] = tmpL[2]; Bl[2 * p + 1][1] = tmpL[3];
            }
            #pragma unroll
            for (int tm = 0; tm < 4; tm++)
                #pragma unroll
                for (int tn = 0; tn < 4; tn++) {
                    mma_bf16(acc[tm][tn], Ah[tm], Bh[tn]);
                    mma_bf16(acc[tm][tn], Ah[tm], Bl[tn]);
                    mma_bf16(acc[tm][tn], Al[tm], Bh[tn]);
                }
        }
        __syncthreads();
    }

    const int qr = lane >> 2;
    const int qc = (lane & 3) * 2;
    #pragma unroll
    for (int tm = 0; tm < 4; tm++) {
        int m0 = wm * 64 + tm * 16 + qr;
        int m1 = m0 + 8;
        bool v0 = (row0 + m0) < cnt;
        bool v1 = (row0 + m1) < cnt;
        float d0 = s_dec[m0], d1 = s_dec[m1];
        float* dst0 = g_f + (size_t)s_idx[m0] * HQ + by * TN;
        float* dst1 = g_f + (size_t)s_idx[m1] * HQ + by * TN;
        #pragma unroll
        for (int tn = 0; tn < 4; tn++) {
            int col = (wn * 4 + tn) * 8 + qc;
            if (v0) *(float2*)(dst0 + col) = make_float2(acc[tm][tn][0] * d0, acc[tm][tn][1] * d0);
            if (v1) *(float2*)(dst1 + col) = make_float2(acc[tm][tn][2] * d1, acc[tm][tn][3] * d1);
        }
    }
}

// -------- csum: child_c_sum = sum_n (f + b_f[r]) * (cc * dec), BW-optimized --------
__global__ __launch_bounds__(256) void csum_kernel(
    const float* __restrict__ child_c, const int* __restrict__ rel_ids,
    const float* __restrict__ b_f)
{
    __shared__ float4 s_part[4][64];
    __shared__ float  s_dec[32];
    __shared__ int    s_rel[32];

    const int b = blockIdx.x, tid = threadIdx.x;
    const int g4 = tid & 63;             // float4 column (g = g4*4..g4*4+3)
    const int ng = tid >> 6;             // 0..3: n-subgroup

    if (tid < NQ) {
        int i = b * NQ + tid;
        s_rel[tid] = rel_ids[i];
        s_dec[tid] = g_dec[i];
    }
    __syncthreads();

    const float4* ff = (const float4*)(g_f     + (size_t)b * NQ * HQ) + g4;
    const float4* cc = (const float4*)(child_c + (size_t)b * NQ * HQ) + g4;

    float4 acc = make_float4(0.f, 0.f, 0.f, 0.f);
    #pragma unroll
    for (int it = 0; it < 8; it++) {
        int n = ng + it * 4;
        float4 f = ff[n * 64];
        float4 c = cc[n * 64];
        float4 bf = *((const float4*)(b_f + s_rel[n] * HQ) + g4);
        float d = s_dec[n];
        acc.x += (f.x + bf.x) * (c.x * d);
        acc.y += (f.y + bf.y) * (c.y * d);
        acc.z += (f.z + bf.z) * (c.z * d);
        acc.w += (f.w + bf.w) * (c.w * d);
    }
    s_part[ng][g4] = acc;
    __syncthreads();

    if (tid < 64) {
        float4 a0 = s_part[0][tid], a1 = s_part[1][tid];
        float4 a2 = s_part[2][tid], a3 = s_part[3][tid];
        float4 r = make_float4(a0.x + a1.x + a2.x + a3.x,
                               a0.y + a1.y + a2.y + a3.y,
                               a0.z + a1.z + a2.z + a3.z,
                               a0.w + a1.w + a2.w + a3.w);
        *((float4*)(g_cs + (size_t)b * HQ) + tid) = r;
    }
}

// -------- gates GEMVs + pointwise epilogue, MB=32 batches per CTA --------
extern __shared__ float smemGate[];

__global__ __launch_bounds__(256) void gates_kernel(
    const float* __restrict__ input_vec,
    const float* __restrict__ b_i, const float* __restrict__ b_o,
    const float* __restrict__ b_u, float* __restrict__ out)
{
    float* comb = smemGate;              // [MB][KQ]
    const int tid = threadIdx.x;
    const int b0  = blockIdx.x * MB;

    #pragma unroll
    for (int k = 0; k < MB * KQ / 4 / 256; k++) {
        int v  = tid + k * 256;
        int m  = v >> 7;
        int k4 = v & 127;
        int bb = b0 + m;
        float4 val;
        if (k4 < 64) val = ((const float4*)(input_vec + (size_t)bb * DINQ))[k4];
        else         val = ((const float4*)(g_hs      + (size_t)bb * HQ))[k4 - 64];
        *((float4*)&comb[m * KQ + k4 * 4]) = val;
    }
    __syncthreads();

    const int g = tid;
    float ai[MB], ao[MB], au[MB];
    #pragma unroll
    for (int m = 0; m < MB; m++) { ai[m] = 0.0f; ao[m] = 0.0f; au[m] = 0.0f; }

    const float* wi = g_WiT + g;
    const float* wo = g_WoT + g;
    const float* wu = g_WuT + g;

    #pragma unroll 2
    for (int k = 0; k < KQ; k++) {
        float vi = wi[(size_t)k * HQ];
        float vo = wo[(size_t)k * HQ];
        float vu = wu[(size_t)k * HQ];
        #pragma unroll
        for (int m = 0; m < MB; m++) {
            float cm = comb[m * KQ + k];
            ai[m] += cm * vi;
            ao[m] += cm * vo;
            au[m] += cm * vu;
        }
    }

    float bi = b_i[g], bo = b_o[g], bu = b_u[g];
    #pragma unroll
    for (int m = 0; m < MB; m++) {
        int bb = b0 + m;
        float iv = 1.0f / (1.0f + __expf(-(ai[m] + bi)));
        float ov = 1.0f / (1.0f + __expf(-(ao[m] + bo)));
        float uv = tanhf(au[m] + bu);
        float c  = iv * uv + g_cs[(size_t)bb * HQ + g];
        float h  = ov * tanhf(c);
        out[(size_t)bb * HQ + g]                   = h;
        out[(size_t)BQ * HQ + (size_t)bb * HQ + g] = c;
    }
}

// -------- launch --------
extern "C" void kernel_launch(void* const* d_in, const int* in_sizes, int n_in,
                              void* d_out, int out_size) {
    const float* input_vec = (const float*)d_in[0];
    const float* child_h   = (const float*)d_in[1];
    const float* child_c   = (const float*)d_in[2];
    const int*   rel_ids   = (const int*)  d_in[3];
    const void*  vmask     =               d_in[4];
    const float* rel_emb   = (const float*)d_in[5];
    const float* W_i       = (const float*)d_in[6];
    const float* b_i       = (const float*)d_in[7];
    const float* W_f       = (const float*)d_in[8];
    const float* b_f       = (const float*)d_in[9];
    const float* W_o       = (const float*)d_in[10];
    const float* b_o       = (const float*)d_in[11];
    const float* W_u       = (const float*)d_in[12];
    const float* b_u       = (const float*)d_in[13];
    const float* w_att     = (const float*)d_in[14];
    const float* b_att     = (const float*)d_in[15];
    float* out = (float*)d_out;

    prep1_kernel<<<(RQ * HQ * HQ + 255) / 256, 256>>>(W_f, W_i, W_o, W_u, vmask);
    prep2_kernel<<<ROWS_TOT / 256, 256>>>(rel_ids, vmask);

    attn_kernel<<<BQ, 256>>>(child_h, rel_ids, rel_emb, w_att, b_att);

    cudaFuncSetAttribute(fgemm_mma_kernel,
                         cudaFuncAttributeMaxDynamicSharedMemorySize, FG_SMEM);
    dim3 ggrid(HQ / TN, ROWS_TOT / TM, RQ);   // (2, 1024, 3), early-exit on empty tiles
    fgemm_mma_kernel<<<ggrid, 256, FG_SMEM>>>(child_h);

    csum_kernel<<<BQ, 256>>>(child_c, rel_ids, b_f);

    cudaFuncSetAttribute(gates_kernel,
                         cudaFuncAttributeMaxDynamicSharedMemorySize, GATES_SMEM);
    gates_kernel<<<BQ / MB, 256, GATES_SMEM>>>(input_vec, b_i, b_o, b_u, out);
}

// round 10
// speedup vs baseline: 1.9175x; 1.1031x over previous
#include <cuda_runtime.h>
#include <cuda_bf16.h>
#include <cstdint>

// Problem constants
#define BQ   4096
#define NQ   32
#define HQ   256
#define DINQ 256
#define RQ   3
#define KQ   (DINQ + HQ)   // 512
#define VIRTUAL_DECAY 0.7f
#define MB   32            // batches per CTA in gate kernel
#define ROWS_TOT (BQ * NQ) // 131072

// mma fgemm tiling
#define TM 128             // rows per CTA tile
#define TN 128             // g per CTA tile
#define KCH 64             // k per staged chunk
#define NCH (HQ / KCH)     // 4 chunks
#define ASTRD 72           // smem row stride in bf16 (144B: 16B-aligned, conflict-free)

// smem byte offsets (fgemm)
#define SMO_IDX 0
#define SMO_DEC 512
#define SMO_AH  1024
#define SMO_AL  (SMO_AH + TM * ASTRD * 2)   // +18432
#define SMO_BH  (SMO_AL + TM * ASTRD * 2)
#define SMO_BL  (SMO_BH + TN * ASTRD * 2)
#define FG_SMEM (SMO_BL + TN * ASTRD * 2)   // 74752 bytes

#define GATES_SMEM (MB * KQ * 4)            // 65536 bytes

// -------- device scratch (no dynamic allocation allowed) --------
__device__ __nv_bfloat16 g_Wfh[RQ * HQ * HQ];  // W_f split, [r][g][h]
__device__ __nv_bfloat16 g_Wfl[RQ * HQ * HQ];
__device__ __nv_bfloat16 g_Ah[(size_t)ROWS_TOT * HQ];  // child_h split hi, [row][k]
__device__ __nv_bfloat16 g_Al[(size_t)ROWS_TOT * HQ];  // child_h split lo
__device__ float g_WiT[KQ * HQ];        // [k][g]
__device__ float g_WoT[KQ * HQ];
__device__ float g_WuT[KQ * HQ];
__device__ float g_hs[BQ * HQ];         // child_h_sum
__device__ float g_cs[BQ * HQ];         // child_c_sum
__device__ float g_f[(size_t)ROWS_TOT * HQ];   // f gate results, [b][n][g]
__device__ float g_dec[ROWS_TOT];       // decay per row
__device__ int   g_idxr[RQ][ROWS_TOT];  // row indices grouped by relation
__device__ int   g_cnt[RQ];
__device__ int   g_mmode;               // virtual_mask storage dtype

__device__ __forceinline__ uint32_t pack_bf16x2(float x, float y) {
    __nv_bfloat16 a = __float2bfloat16_rn(x);
    __nv_bfloat16 b = __float2bfloat16_rn(y);
    return (uint32_t)__bfloat16_as_ushort(a) | ((uint32_t)__bfloat16_as_ushort(b) << 16);
}
__device__ __forceinline__ void mma_bf16(float* c, const uint32_t* a, const uint32_t* b) {
    asm volatile(
        "mma.sync.aligned.m16n8k16.row.col.f32.bf16.bf16.f32 "
        "{%0,%1,%2,%3}, {%4,%5,%6,%7}, {%8,%9}, {%0,%1,%2,%3};"
        : "+f"(c[0]), "+f"(c[1]), "+f"(c[2]), "+f"(c[3])
        : "r"(a[0]), "r"(a[1]), "r"(a[2]), "r"(a[3]), "r"(b[0]), "r"(b[1]));
}
__device__ __forceinline__ void ldsm_x4(uint32_t* r, uint32_t addr) {
    asm volatile("ldmatrix.sync.aligned.m8n8.x4.shared.b16 {%0,%1,%2,%3}, [%4];"
                 : "=r"(r[0]), "=r"(r[1]), "=r"(r[2]), "=r"(r[3]) : "r"(addr));
}
__device__ __forceinline__ void cpasync16(uint32_t dst, const void* src) {
    asm volatile("cp.async.cg.shared.global [%0], [%1], 16;\n" :: "r"(dst), "l"(src));
}

__device__ __forceinline__ float load_dec(const void* vmask, int i, int mmode) {
    bool mv;
    if (mmode == 0)      mv = ((const int*)vmask)[i] != 0;
    else if (mmode == 1) mv = ((const unsigned char*)vmask)[i] != 0;
    else                 mv = ((const float*)vmask)[i] != 0.0f;
    return mv ? VIRTUAL_DECAY : 1.0f;
}

// -------- prep1: weight split + gate transposes + mask dtype + zero counters --------
__global__ __launch_bounds__(256) void prep1_kernel(
    const float* __restrict__ Wf, const float* __restrict__ Wi,
    const float* __restrict__ Wo, const float* __restrict__ Wu,
    const void* __restrict__ vmask)
{
    int idx = blockIdx.x * 256 + threadIdx.x;
    if (idx < RQ * HQ * HQ) {
        float x = Wf[idx];
        __nv_bfloat16 h = __float2bfloat16_rn(x);
        float r = x - __bfloat162float(h);
        g_Wfh[idx] = h;
        g_Wfl[idx] = __float2bfloat16_rn(r);
    }
    if (idx < KQ * HQ) {
        int g = idx & (HQ - 1);
        int k = idx >> 8;
        g_WiT[idx] = Wi[g * KQ + k];
        g_WoT[idx] = Wo[g * KQ + k];
        g_WuT[idx] = Wu[g * KQ + k];
    }
    if (blockIdx.x == 0) {
        __shared__ int fl[2];
        int tid = threadIdx.x;
        if (tid < 2) fl[tid] = 0;
        if (tid < RQ) g_cnt[tid] = 0;
        __syncthreads();
        const unsigned char* mb = (const unsigned char*)vmask;
        for (int off = tid; off < 8192; off += 256) {
            int m = off & 3;
            unsigned char v = mb[off];
            if (m && v) {
                fl[0] = 1;                                     // non-aligned nonzero -> not i32
                if ((m == 2 && v == 0x80u) || (m == 3 && v == 0x3Fu))
                    fl[1] = 1;                                 // 1.0f byte pattern -> f32
            }
        }
        __syncthreads();
        if (tid == 0) g_mmode = fl[1] ? 2 : (fl[0] ? 1 : 0);   // 0=i32, 1=u8, 2=f32
    }
}

// -------- prep2: decay + counting-sort rows by relation --------
__global__ __launch_bounds__(256) void prep2_kernel(
    const int* __restrict__ rel_ids, const void* __restrict__ vmask)
{
    int i = blockIdx.x * 256 + threadIdx.x;
    if (i >= ROWS_TOT) return;
    int mmode = g_mmode;
    g_dec[i] = load_dec(vmask, i, mmode);
    int r = rel_ids[i];
    int pos = atomicAdd(&g_cnt[r], 1);
    g_idxr[r][pos] = i;
}

// -------- attn: attention + child_h_sum + child_h bf16 hi/lo split --------
__global__ __launch_bounds__(256) void attn_kernel(
    const float* __restrict__ child_h, const int* __restrict__ rel_ids,
    const float* __restrict__ rel_emb, const float* __restrict__ w_att,
    const float* __restrict__ b_att)
{
    __shared__ float sch[NQ][264];        // decayed child_h
    __shared__ float s_sc[32], s_dec[32];
    __shared__ int   s_rel[32];

    const int b = blockIdx.x, tid = threadIdx.x;
    const int warp = tid >> 5, lane = tid & 31;

    if (tid < NQ) {
        int i = b * NQ + tid;
        s_rel[tid] = rel_ids[i];
        s_dec[tid] = g_dec[i];
    }
    __syncthreads();

    {
        const float4* gh = (const float4*)(child_h + (size_t)b * NQ * HQ);
        #pragma unroll
        for (int k = 0; k < 8; k++) {
            int v  = tid + k * 256;
            int n  = v >> 6;
            int h4 = v & 63;
            float4 a = gh[v];
            // bf16 hi/lo split of the RAW value (decay applied in fgemm epilogue)
            uint32_t h01 = pack_bf16x2(a.x, a.y);
            uint32_t h23 = pack_bf16x2(a.z, a.w);
            uint32_t l01 = pack_bf16x2(a.x - __bfloat162float(__float2bfloat16_rn(a.x)),
                                       a.y - __bfloat162float(__float2bfloat16_rn(a.y)));
            uint32_t l23 = pack_bf16x2(a.z - __bfloat162float(__float2bfloat16_rn(a.z)),
                                       a.w - __bfloat162float(__float2bfloat16_rn(a.w)));
            size_t ro = (size_t)(b * NQ + n) * HQ + h4 * 4;
            *(uint2*)(g_Ah + ro) = make_uint2(h01, h23);
            *(uint2*)(g_Al + ro) = make_uint2(l01, l23);
            float d = s_dec[n];
            a.x *= d; a.y *= d; a.z *= d; a.w *= d;
            *((float4*)&sch[n][h4 * 4]) = a;
        }
    }
    __syncthreads();

    {
        float batt = b_att[0];
        for (int nn = warp * 4; nn < warp * 4 + 4; nn++) {
            const float* rrow = rel_emb + s_rel[nn] * HQ;
            float p = 0.0f;
            #pragma unroll
            for (int h = lane; h < HQ; h += 32)
                p += (rrow[h] + sch[nn][h]) * w_att[h];
            #pragma unroll
            for (int o = 16; o; o >>= 1) p += __shfl_xor_sync(0xffffffffu, p, o);
            if (lane == 0) s_sc[nn] = p + batt;
        }
    }
    __syncthreads();

    if (warp == 0) {
        float s = s_sc[lane], m = s;
        #pragma unroll
        for (int o = 16; o; o >>= 1) m = fmaxf(m, __shfl_xor_sync(0xffffffffu, m, o));
        float e = __expf(s - m), su = e;
        #pragma unroll
        for (int o = 16; o; o >>= 1) su += __shfl_xor_sync(0xffffffffu, su, o);
        s_sc[lane] = e / su;
    }
    __syncthreads();

    {
        int g = tid;
        float acc = 0.0f;
        #pragma unroll
        for (int n = 0; n < NQ; n++)
            acc += s_sc[n] * sch[n][g];
        g_hs[(size_t)b * HQ + g] = acc;
    }
}

// -------- fgemm via mma.sync bf16 (3 products), cp.async staging, 2 CTAs/SM --------
extern __shared__ char smF[];

__global__ __launch_bounds__(256, 2) void fgemm_mma_kernel()
{
    const int by = blockIdx.x;           // g tile (0..1)
    const int bx = blockIdx.y;           // row tile
    const int bz = blockIdx.z;           // relation
    const int cnt = g_cnt[bz];
    const int row0 = bx * TM;
    if (row0 >= cnt) return;

    int*   s_idx = (int*)(smF + SMO_IDX);
    float* s_dec = (float*)(smF + SMO_DEC);

    const int tid  = threadIdx.x;
    const int lane = tid & 31;
    const int wid  = tid >> 5;
    const int wm   = wid >> 2;           // 0..1  (m half)
    const int wn   = wid & 3;            // 0..3  (n quarter, 32 g each)

    const uint32_t smem_base = (uint32_t)__cvta_generic_to_shared(smF);

    if (tid < TM) {
        int rr = row0 + tid;
        if (rr >= cnt) rr = cnt - 1;
        int gi = g_idxr[bz][rr];
        s_idx[tid] = gi;
        s_dec[tid] = g_dec[gi];
    }
    __syncthreads();

    // stage one chunk entirely with cp.async (A gathered rows, B direct)
    auto stage = [&](int kc) {
        #pragma unroll
        for (int it = 0; it < 4; it++) {
            int v = tid + it * 256;      // 0..1023
            int m = v >> 3;              // row 0..127
            int c = v & 7;               // 16B unit within 128B chunk row
            const __nv_bfloat16* srcH = g_Ah + (size_t)s_idx[m] * HQ + kc * KCH + c * 8;
            const __nv_bfloat16* srcL = g_Al + (size_t)s_idx[m] * HQ + kc * KCH + c * 8;
            uint32_t dst = smem_base + SMO_AH + (uint32_t)(m * (ASTRD * 2) + c * 16);
            cpasync16(dst, srcH);
            cpasync16(dst + (SMO_AL - SMO_AH), srcL);
        }
        #pragma unroll
        for (int it = 0; it < 4; it++) {
            int v = tid + it * 256;
            int n = v >> 3;              // g row 0..127
            int c = v & 7;
            size_t src = ((size_t)(bz * HQ + by * TN + n)) * HQ + kc * KCH + c * 8;
            uint32_t dst = smem_base + SMO_BH + (uint32_t)(n * (ASTRD * 2) + c * 16);
            cpasync16(dst, g_Wfh + src);
            cpasync16(dst + (SMO_BL - SMO_BH), g_Wfl + src);
        }
        asm volatile("cp.async.commit_group;\n");
    };

    float acc[4][4][4];
    #pragma unroll
    for (int a = 0; a < 4; a++)
        #pragma unroll
        for (int b = 0; b < 4; b++)
            #pragma unroll
            for (int c = 0; c < 4; c++) acc[a][b][c] = 0.0f;

    const int arow  = lane & 15;
    const int acol8 = (lane >> 4) << 3;
    const int brow  = (lane & 7) + ((lane >> 4) << 3);
    const int bcol8 = ((lane >> 3) & 1) << 3;

    for (int kc = 0; kc < NCH; kc++) {
        stage(kc);
        asm volatile("cp.async.wait_group 0;\n");
        __syncthreads();

        #pragma unroll
        for (int tk = 0; tk < 4; tk++) {
            const int k0 = tk * 16;
            uint32_t Bh[4][2], Bl[4][2];
            #pragma unroll
            for (int p = 0; p < 2; p++) {
                int r = wn * 32 + p * 16 + brow;
                uint32_t bo = smem_base + SMO_BH + (uint32_t)(r * (ASTRD * 2) + (k0 + bcol8) * 2);
                uint32_t tmpH[4], tmpL[4];
                ldsm_x4(tmpH, bo);
                ldsm_x4(tmpL, bo + (SMO_BL - SMO_BH));
                Bh[2 * p][0] = tmpH[0]; Bh[2 * p][1] = tmpH[1];
                Bh[2 * p + 1][0] = tmpH[2]; Bh[2 * p + 1][1] = tmpH[3];
                Bl[2 * p][0] = tmpL[0]; Bl[2 * p][1] = tmpL[1];
                Bl[2 * p + 1][0] = tmpL[2]; Bl[2 * p + 1][1] = tmpL[3];
            }
            #pragma unroll
            for (int tm = 0; tm < 4; tm++) {
                int r = wm * 64 + tm * 16 + arow;
                uint32_t ao = smem_base + SMO_AH + (uint32_t)(r * (ASTRD * 2) + (k0 + acol8) * 2);
                uint32_t Ah[4], Al[4];
                ldsm_x4(Ah, ao);
                ldsm_x4(Al, ao + (SMO_AL - SMO_AH));
                #pragma unroll
                for (int tn = 0; tn < 4; tn++) {
                    mma_bf16(acc[tm][tn], Ah, Bh[tn]);
                    mma_bf16(acc[tm][tn], Ah, Bl[tn]);
                    mma_bf16(acc[tm][tn], Al, Bh[tn]);
                }
            }
        }
        __syncthreads();
    }

    const int qr = lane >> 2;
    const int qc = (lane & 3) * 2;
    #pragma unroll
    for (int tm = 0; tm < 4; tm++) {
        int m0 = wm * 64 + tm * 16 + qr;
        int m1 = m0 + 8;
        bool v0 = (row0 + m0) < cnt;
        bool v1 = (row0 + m1) < cnt;
        float d0 = s_dec[m0], d1 = s_dec[m1];
        float* dst0 = g_f + (size_t)s_idx[m0] * HQ + by * TN;
        float* dst1 = g_f + (size_t)s_idx[m1] * HQ + by * TN;
        #pragma unroll
        for (int tn = 0; tn < 4; tn++) {
            int col = (wn * 4 + tn) * 8 + qc;
            if (v0) *(float2*)(dst0 + col) = make_float2(acc[tm][tn][0] * d0, acc[tm][tn][1] * d0);
            if (v1) *(float2*)(dst1 + col) = make_float2(acc[tm][tn][2] * d1, acc[tm][tn][3] * d1);
        }
    }
}

// -------- csum: child_c_sum = sum_n (f + b_f[r]) * (cc * dec), BW-optimized --------
__global__ __launch_bounds__(256) void csum_kernel(
    const float* __restrict__ child_c, const int* __restrict__ rel_ids,
    const float* __restrict__ b_f)
{
    __shared__ float4 s_part[4][64];
    __shared__ float  s_dec[32];
    __shared__ int    s_rel[32];

    const int b = blockIdx.x, tid = threadIdx.x;
    const int g4 = tid & 63;             // float4 column
    const int ng = tid >> 6;             // 0..3: n-subgroup

    if (tid < NQ) {
        int i = b * NQ + tid;
        s_rel[tid] = rel_ids[i];
        s_dec[tid] = g_dec[i];
    }
    __syncthreads();

    const float4* ff = (const float4*)(g_f     + (size_t)b * NQ * HQ) + g4;
    const float4* cc = (const float4*)(child_c + (size_t)b * NQ * HQ) + g4;

    float4 acc = make_float4(0.f, 0.f, 0.f, 0.f);
    #pragma unroll
    for (int it = 0; it < 8; it++) {
        int n = ng + it * 4;
        float4 f = ff[n * 64];
        float4 c = cc[n * 64];
        float4 bf = *((const float4*)(b_f + s_rel[n] * HQ) + g4);
        float d = s_dec[n];
        acc.x += (f.x + bf.x) * (c.x * d);
        acc.y += (f.y + bf.y) * (c.y * d);
        acc.z += (f.z + bf.z) * (c.z * d);
        acc.w += (f.w + bf.w) * (c.w * d);
    }
    s_part[ng][g4] = acc;
    __syncthreads();

    if (tid < 64) {
        float4 a0 = s_part[0][tid], a1 = s_part[1][tid];
        float4 a2 = s_part[2][tid], a3 = s_part[3][tid];
        float4 r = make_float4(a0.x + a1.x + a2.x + a3.x,
                               a0.y + a1.y + a2.y + a3.y,
                               a0.z + a1.z + a2.z + a3.z,
                               a0.w + a1.w + a2.w + a3.w);
        *((float4*)(g_cs + (size_t)b * HQ) + tid) = r;
    }
}

// -------- gates GEMVs + pointwise epilogue, MB=32 batches per CTA --------
extern __shared__ float smemGate[];

__global__ __launch_bounds__(256) void gates_kernel(
    const float* __restrict__ input_vec,
    const float* __restrict__ b_i, const float* __restrict__ b_o,
    const float* __restrict__ b_u, float* __restrict__ out)
{
    float* comb = smemGate;              // [MB][KQ]
    const int tid = threadIdx.x;
    const int b0  = blockIdx.x * MB;

    #pragma unroll
    for (int k = 0; k < MB * KQ / 4 / 256; k++) {
        int v  = tid + k * 256;
        int m  = v >> 7;
        int k4 = v & 127;
        int bb = b0 + m;
        float4 val;
        if (k4 < 64) val = ((const float4*)(input_vec + (size_t)bb * DINQ))[k4];
        else         val = ((const float4*)(g_hs      + (size_t)bb * HQ))[k4 - 64];
        *((float4*)&comb[m * KQ + k4 * 4]) = val;
    }
    __syncthreads();

    const int g = tid;
    float ai[MB], ao[MB], au[MB];
    #pragma unroll
    for (int m = 0; m < MB; m++) { ai[m] = 0.0f; ao[m] = 0.0f; au[m] = 0.0f; }

    const float* wi = g_WiT + g;
    const float* wo = g_WoT + g;
    const float* wu = g_WuT + g;

    #pragma unroll 2
    for (int k = 0; k < KQ; k++) {
        float vi = wi[(size_t)k * HQ];
        float vo = wo[(size_t)k * HQ];
        float vu = wu[(size_t)k * HQ];
        #pragma unroll
        for (int m = 0; m < MB; m++) {
            float cm = comb[m * KQ + k];
            ai[m] += cm * vi;
            ao[m] += cm * vo;
            au[m] += cm * vu;
        }
    }

    float bi = b_i[g], bo = b_o[g], bu = b_u[g];
    #pragma unroll
    for (int m = 0; m < MB; m++) {
        int bb = b0 + m;
        float iv = 1.0f / (1.0f + __expf(-(ai[m] + bi)));
        float ov = 1.0f / (1.0f + __expf(-(ao[m] + bo)));
        float uv = tanhf(au[m] + bu);
        float c  = iv * uv + g_cs[(size_t)bb * HQ + g];
        float h  = ov * tanhf(c);
        out[(size_t)bb * HQ + g]                   = h;
        out[(size_t)BQ * HQ + (size_t)bb * HQ + g] = c;
    }
}

// -------- launch --------
extern "C" void kernel_launch(void* const* d_in, const int* in_sizes, int n_in,
                              void* d_out, int out_size) {
    const float* input_vec = (const float*)d_in[0];
    const float* child_h   = (const float*)d_in[1];
    const float* child_c   = (const float*)d_in[2];
    const int*   rel_ids   = (const int*)  d_in[3];
    const void*  vmask     =               d_in[4];
    const float* rel_emb   = (const float*)d_in[5];
    const float* W_i       = (const float*)d_in[6];
    const float* b_i       = (const float*)d_in[7];
    const float* W_f       = (const float*)d_in[8];
    const float* b_f       = (const float*)d_in[9];
    const float* W_o       = (const float*)d_in[10];
    const float* b_o       = (const float*)d_in[11];
    const float* W_u       = (const float*)d_in[12];
    const float* b_u       = (const float*)d_in[13];
    const float* w_att     = (const float*)d_in[14];
    const float* b_att     = (const float*)d_in[15];
    float* out = (float*)d_out;

    prep1_kernel<<<(RQ * HQ * HQ + 255) / 256, 256>>>(W_f, W_i, W_o, W_u, vmask);
    prep2_kernel<<<ROWS_TOT / 256, 256>>>(rel_ids, vmask);

    attn_kernel<<<BQ, 256>>>(child_h, rel_ids, rel_emb, w_att, b_att);

    cudaFuncSetAttribute(fgemm_mma_kernel,
                         cudaFuncAttributeMaxDynamicSharedMemorySize, FG_SMEM);
    dim3 ggrid(HQ / TN, ROWS_TOT / TM, RQ);   // (2, 1024, 3), early-exit on empty tiles
    fgemm_mma_kernel<<<ggrid, 256, FG_SMEM>>>();

    csum_kernel<<<BQ, 256>>>(child_c, rel_ids, b_f);

    cudaFuncSetAttribute(gates_kernel,
                         cudaFuncAttributeMaxDynamicSharedMemorySize, GATES_SMEM);
    gates_kernel<<<BQ / MB, 256, GATES_SMEM>>>(input_vec, b_i, b_o, b_u, out);
}